// round 1
// baseline (speedup 1.0000x reference)
#include <cuda_runtime.h>
#include <cuda_bf16.h>
#include <math.h>

// ---------------- problem constants (fixed shapes) ----------------
#define NUTT   2000          // utterances per modality
#define NROW   6000          // 3 * NUTT graph nodes
#define NCOL   200           // n_dim == nhidden
#define NLAY   8
#define ALPHA  0.1f
#define DIA_L  100
#define DIA_B  20

// ---------------- GEMM tiling ----------------
#define BM 64
#define BN 200               // full output width -> adj streamed exactly once
#define BK 16
#define NTHREADS 224         // 7 warps; 200 active compute threads (8 x 25)
#define KSPLIT 4
#define KCHUNK 1500          // 6000 / KSPLIT

// ---------------- scratch (no allocations allowed) ----------------
__device__ float g_x   [NROW * NCOL];
__device__ float g_h0  [NROW * NCOL];
__device__ float g_h   [NROW * NCOL];
__device__ float g_hi  [NROW * NCOL];
__device__ float g_part[KSPLIT * NROW * NCOL];

enum { EP_NONE = 0, EP_BIAS = 1, EP_SPK = 2, EP_RELU = 3, EP_GCNII = 4 };

// ---------------- packed f32x2 helpers (Blackwell FFMA2) ----------------
__device__ __forceinline__ unsigned long long pack2(float a, float b) {
    unsigned long long r;
    asm("mov.b64 %0, {%1, %2};" : "=l"(r) : "f"(a), "f"(b));
    return r;
}
__device__ __forceinline__ void ffma2(unsigned long long& d,
                                      unsigned long long a, unsigned long long b) {
    asm("fma.rn.f32x2 %0, %1, %2, %0;" : "+l"(d) : "l"(a), "l"(b));
}
__device__ __forceinline__ float2 unpack2(unsigned long long v) {
    float2 f;
    asm("mov.b64 {%0, %1}, %2;" : "=f"(f.x), "=f"(f.y) : "l"(v));
    return f;
}

// =====================================================================
// Generic SGEMM: C[M, 200] = A0[M, K0] @ B0[K0, 200] (+ A1[M,K1] @ B1)
// with fused epilogue. Optional K-split along A0 via blockIdx.y
// (each split writes its own partial buffer C + by * NROW*NCOL).
// Thread layout: (tr 0..7) x (tc 0..24); thread tile 8 rows x 8 cols,
// cols picked as 4 f32-pairs at pair-index (tc + 25*p), p=0..3.
// =====================================================================
template <int EP>
__global__ __launch_bounds__(NTHREADS, 2)
void sgemm_ep(const float* __restrict__ A0, int lda0, int K0,
              const float* __restrict__ B0,
              const float* __restrict__ A1, int lda1, int K1,
              const float* __restrict__ B1,
              int M, float* __restrict__ C, int kchunk,
              const float* __restrict__ bias,
              const float* __restrict__ aux0,   // EP_SPK: qmask | EP_GCNII: hi
              const float* __restrict__ aux1,   // EP_SPK: spk_emb | EP_GCNII: h0
              float theta)
{
    __shared__ __align__(16) float As[BK][BM];   // transposed: [kk][row]
    __shared__ __align__(16) float Bs[BK][BN];

    const int tid  = threadIdx.x;
    const int tr   = tid / 25;           // 0..8 (8 => loader-only thread)
    const int tc   = tid % 25;
    const int row0 = blockIdx.x * BM;

    unsigned long long acc[8][4];
#pragma unroll
    for (int r = 0; r < 8; r++)
#pragma unroll
        for (int p = 0; p < 4; p++) acc[r][p] = 0ull;

    const int ks = blockIdx.y * kchunk;
    const int ke = (ks + kchunk < K0) ? (ks + kchunk) : K0;
    float* Cout = C + (size_t)blockIdx.y * (size_t)(NROW * NCOL);

    for (int seg = 0; seg < 2; seg++) {
        const float* A;
        const float* B;
        int lda, kbeg, kend;
        if (seg == 0) { A = A0; B = B0; lda = lda0; kbeg = ks; kend = ke; }
        else          { if (A1 == nullptr) break;
                        A = A1; B = B1; lda = lda1; kbeg = 0;  kend = K1; }

        for (int kb = kbeg; kb < kend; kb += BK) {
            // stage A tile (transposed into As[kk][row])
            for (int idx = tid; idx < BM * BK; idx += NTHREADS) {
                int r  = idx / BK;
                int kk = idx % BK;
                int gr = row0 + r;
                int gk = kb + kk;
                float v = 0.0f;
                if (gr < M && gk < kend) v = A[(size_t)gr * lda + gk];
                As[kk][r] = v;
            }
            // stage B tile
            for (int idx = tid; idx < BN * BK; idx += NTHREADS) {
                int kk = idx / BN;
                int c  = idx % BN;
                int gk = kb + kk;
                float v = 0.0f;
                if (gk < kend) v = B[(size_t)gk * BN + c];
                Bs[kk][c] = v;
            }
            __syncthreads();

            if (tr < 8) {
#pragma unroll
                for (int kk = 0; kk < BK; kk++) {
                    float4 a0 = *(const float4*)&As[kk][tr * 8];
                    float4 a1 = *(const float4*)&As[kk][tr * 8 + 4];
                    unsigned long long b[4];
#pragma unroll
                    for (int p = 0; p < 4; p++)
                        b[p] = *(const unsigned long long*)&Bs[kk][2 * (tc + 25 * p)];
                    float ar[8] = {a0.x, a0.y, a0.z, a0.w, a1.x, a1.y, a1.z, a1.w};
#pragma unroll
                    for (int r = 0; r < 8; r++) {
                        unsigned long long a2 = pack2(ar[r], ar[r]);
#pragma unroll
                        for (int p = 0; p < 4; p++) ffma2(acc[r][p], a2, b[p]);
                    }
                }
            }
            __syncthreads();
        }
    }

    // ---------------- epilogue ----------------
    if (tr < 8) {
#pragma unroll
        for (int r = 0; r < 8; r++) {
            int row = row0 + tr * 8 + r;
            if (row >= M) continue;

            int spk = 0;
            if (EP == EP_SPK) {
                int bI = row / DIA_L;
                int tI = row % DIA_L;
                const float* q = aux0 + ((size_t)tI * DIA_B + bI) * 2;
                spk = (q[1] > q[0]) ? 1 : 0;
            }
#pragma unroll
            for (int p = 0; p < 4; p++) {
                int col = 2 * (tc + 25 * p);
                float2 v = unpack2(acc[r][p]);
                if (EP == EP_BIAS) {
                    v.x += bias[col];
                    v.y += bias[col + 1];
                } else if (EP == EP_SPK) {
                    v.x += bias[col]     + aux1[spk * NCOL + col];
                    v.y += bias[col + 1] + aux1[spk * NCOL + col + 1];
                } else if (EP == EP_RELU) {
                    v.x = fmaxf(v.x + bias[col], 0.0f);
                    v.y = fmaxf(v.y + bias[col + 1], 0.0f);
                } else if (EP == EP_GCNII) {
                    float2 hi  = *(const float2*)&aux0[(size_t)row * NCOL + col];
                    float2 h0v = *(const float2*)&aux1[(size_t)row * NCOL + col];
                    float rx = (1.0f - ALPHA) * hi.x + ALPHA * h0v.x;
                    float ry = (1.0f - ALPHA) * hi.y + ALPHA * h0v.y;
                    v.x = fmaxf(theta * v.x + (1.0f - theta) * rx, 0.0f);
                    v.y = fmaxf(theta * v.y + (1.0f - theta) * ry, 0.0f);
                }
                *(float2*)&Cout[(size_t)row * NCOL + col] = v;
            }
        }
    }
}

// sum the KSPLIT partial buffers -> g_hi
__global__ void reduce4_kernel() {
    int i = blockIdx.x * blockDim.x + threadIdx.x;
    const int S = NROW * NCOL;          // 1,200,000
    if (i < S / 4) {
        const float4* p = (const float4*)g_part;
        float4 v0 = p[i];
        float4 v1 = p[i + S / 4];
        float4 v2 = p[i + 2 * (S / 4)];
        float4 v3 = p[i + 3 * (S / 4)];
        float4 o;
        o.x = v0.x + v1.x + v2.x + v3.x;
        o.y = v0.y + v1.y + v2.y + v3.y;
        o.z = v0.z + v1.z + v2.z + v3.z;
        o.w = v0.w + v1.w + v2.w + v3.w;
        ((float4*)g_hi)[i] = o;
    }
}

// out[i, m*400 + j] = (j<200 ? x : h)[m*2000 + i, j%200]
__global__ void assemble_kernel(float* __restrict__ out) {
    int idx = blockIdx.x * blockDim.x + threadIdx.x;
    if (idx < NUTT * 1200) {
        int i = idx / 1200;
        int c = idx % 1200;
        int m = c / 400;
        int j = c % 400;
        const float* src = (j < 200) ? g_x : g_h;
        out[idx] = src[(size_t)(m * NUTT + i) * NCOL + (j % NCOL)];
    }
}

// =====================================================================
extern "C" void kernel_launch(void* const* d_in, const int* in_sizes, int n_in,
                              void* d_out, int out_size)
{
    const float* a     = (const float*)d_in[0];
    const float* v     = (const float*)d_in[1];
    const float* l     = (const float*)d_in[2];
    const float* qmask = (const float*)d_in[3];
    const float* adj   = (const float*)d_in[4];
    const float* Wa    = (const float*)d_in[5];
    const float* ba    = (const float*)d_in[6];
    const float* Wv    = (const float*)d_in[7];
    const float* bv    = (const float*)d_in[8];
    const float* Wl    = (const float*)d_in[9];
    const float* bl    = (const float*)d_in[10];
    const float* spk   = (const float*)d_in[11];
    const float* W0    = (const float*)d_in[12];
    const float* b0    = (const float*)d_in[13];
    const float* convW = (const float*)d_in[14];
    float* out = (float*)d_out;

    float *gx, *gh0, *gh, *ghi, *gpart;
    cudaGetSymbolAddress((void**)&gx,    g_x);
    cudaGetSymbolAddress((void**)&gh0,   g_h0);
    cudaGetSymbolAddress((void**)&gh,    g_h);
    cudaGetSymbolAddress((void**)&ghi,   g_hi);
    cudaGetSymbolAddress((void**)&gpart, g_part);

    const int gProj = (NUTT + BM - 1) / BM;   // 32
    const int gFull = (NROW + BM - 1) / BM;   // 94

    // modality projections -> g_x
    sgemm_ep<EP_BIAS><<<dim3(gProj, 1), NTHREADS>>>(
        a, 300, 300, Wa, nullptr, 0, 0, nullptr,
        NUTT, gx, 300, ba, nullptr, nullptr, 0.0f);
    sgemm_ep<EP_BIAS><<<dim3(gProj, 1), NTHREADS>>>(
        v, 342, 342, Wv, nullptr, 0, 0, nullptr,
        NUTT, gx + (size_t)NUTT * NCOL, 342, bv, nullptr, nullptr, 0.0f);
    sgemm_ep<EP_SPK><<<dim3(gProj, 1), NTHREADS>>>(
        l, 1024, 1024, Wl, nullptr, 0, 0, nullptr,
        NUTT, gx + (size_t)2 * NUTT * NCOL, 1024, bl, qmask, spk, 0.0f);

    // h0 = relu(x @ W0 + b0)
    sgemm_ep<EP_RELU><<<dim3(gFull, 1), NTHREADS>>>(
        gx, NCOL, NCOL, W0, nullptr, 0, 0, nullptr,
        NROW, gh0, NCOL, b0, nullptr, nullptr, 0.0f);

    // GCNII layers
    for (int lay = 0; lay < NLAY; lay++) {
        float theta = logf(0.5f / (float)(lay + 1) + 1.0f);
        const float* h_in = (lay == 0) ? gh0 : gh;

        // hi partials = adj @ h  (K split 4 ways)
        sgemm_ep<EP_NONE><<<dim3(gFull, KSPLIT), NTHREADS>>>(
            adj, NROW, NROW, h_in, nullptr, 0, 0, nullptr,
            NROW, gpart, KCHUNK, nullptr, nullptr, nullptr, 0.0f);
        reduce4_kernel<<<(NROW * NCOL / 4 + 255) / 256, 256>>>();

        // h = relu(theta * (hi@W1 + h0@W2) + (1-theta)*(0.9*hi + 0.1*h0))
        const float* W1 = convW + (size_t)lay * 400 * NCOL;
        const float* W2 = W1 + (size_t)NCOL * NCOL;
        sgemm_ep<EP_GCNII><<<dim3(gFull, 1), NTHREADS>>>(
            ghi, NCOL, NCOL, W1, gh0, NCOL, NCOL, W2,
            NROW, gh, NCOL, nullptr, ghi, gh0, theta);
    }

    // fuse modalities back: [2000, 1200]
    assemble_kernel<<<(NUTT * 1200 + 255) / 256, 256>>>(out);
}

// round 5
// speedup vs baseline: 4.7683x; 4.7683x over previous
#include <cuda_runtime.h>
#include <cuda_bf16.h>
#include <math.h>
#include <stdint.h>

// ---------------- problem constants ----------------
#define NUTT   2000
#define NROW   6000
#define NCOL   200
#define NLAY   8

// ---------------- MMA kernel geometry ----------------
#define BMM   128            // CTA rows
#define BNN   224            // CTA cols (padded from 200)
#define BKK   32             // K per stage
#define NST   3              // pipeline stages
#define SA_H  0u
#define SA_L  8192u
#define SB_H  16384u
#define SB_L  30720u
#define STAGE 45056u         // 2*8192 + 2*14336
#define DSMEM (3*45056 + 1024)

// ---------------- scratch (device globals; no runtime alloc) ----------------
__device__ __align__(256) float g_x   [NROW * NCOL];
__device__ __align__(256) float g_h0  [NROW * NCOL];
__device__ __align__(256) float g_h   [NROW * NCOL];
__device__ __align__(256) float g_hi  [NROW * NCOL];
__device__ __align__(256) float g_part[3 * NROW * NCOL];

__device__ __align__(256) __nv_bfloat16 g_adjh[NROW * NROW];
__device__ __align__(256) __nv_bfloat16 g_adjl[NROW * NROW];
__device__ __align__(256) __nv_bfloat16 g_hTh [NCOL * NROW];
__device__ __align__(256) __nv_bfloat16 g_hTl [NCOL * NROW];
__device__ __align__(256) __nv_bfloat16 g_Sh  [NROW * 2 * NCOL];
__device__ __align__(256) __nv_bfloat16 g_Sl  [NROW * 2 * NCOL];
__device__ __align__(256) __nv_bfloat16 g_WTh [NCOL * 2 * NCOL];
__device__ __align__(256) __nv_bfloat16 g_WTl [NCOL * 2 * NCOL];
__device__ __align__(256) __nv_bfloat16 g_W0Th[NCOL * NCOL];
__device__ __align__(256) __nv_bfloat16 g_W0Tl[NCOL * NCOL];
__device__ __align__(256) __nv_bfloat16 g_xh  [NROW * NCOL];
__device__ __align__(256) __nv_bfloat16 g_xl  [NROW * NCOL];

__device__ __align__(256) __nv_bfloat16 g_ah_ [2000 * 304];
__device__ __align__(256) __nv_bfloat16 g_al_ [2000 * 304];
__device__ __align__(256) __nv_bfloat16 g_vh_ [2000 * 352];
__device__ __align__(256) __nv_bfloat16 g_vl_ [2000 * 352];
__device__ __align__(256) __nv_bfloat16 g_lh_ [2000 * 1024];
__device__ __align__(256) __nv_bfloat16 g_ll_ [2000 * 1024];
__device__ __align__(256) __nv_bfloat16 g_WaTh[NCOL * 304];
__device__ __align__(256) __nv_bfloat16 g_WaTl[NCOL * 304];
__device__ __align__(256) __nv_bfloat16 g_WvTh[NCOL * 352];
__device__ __align__(256) __nv_bfloat16 g_WvTl[NCOL * 352];
__device__ __align__(256) __nv_bfloat16 g_WlTh[NCOL * 1024];
__device__ __align__(256) __nv_bfloat16 g_WlTl[NCOL * 1024];

// ---------------- helpers ----------------
__device__ __forceinline__ uint32_t smem_u32(const void* p) {
    uint32_t a;
    asm("{ .reg .u64 t; cvta.to.shared.u64 t, %1; cvt.u32.u64 %0, t; }" : "=r"(a) : "l"(p));
    return a;
}
// 64-byte-row swizzle: XOR 16B-chunk index (bits 4-5) with row low bits (bits 6-7).
// Conflict-free for 8-consecutive-row ldmatrix phases AND 4-chunk cp.async stores.
__device__ __forceinline__ uint32_t swz(uint32_t off) {
    return off ^ ((off >> 2) & 0x30u);
}
__device__ __forceinline__ void ldsm4(uint32_t* r, uint32_t a) {
    asm volatile("ldmatrix.sync.aligned.m8n8.x4.shared.b16 {%0,%1,%2,%3}, [%4];"
                 : "=r"(r[0]), "=r"(r[1]), "=r"(r[2]), "=r"(r[3]) : "r"(a));
}
__device__ __forceinline__ void ldsm2(uint32_t* r, uint32_t a) {
    asm volatile("ldmatrix.sync.aligned.m8n8.x2.shared.b16 {%0,%1}, [%2];"
                 : "=r"(r[0]), "=r"(r[1]) : "r"(a));
}
__device__ __forceinline__ void mma16816(float* d, const uint32_t* a, const uint32_t* b) {
    asm volatile("mma.sync.aligned.m16n8k16.row.col.f32.bf16.bf16.f32 "
                 "{%0,%1,%2,%3}, {%4,%5,%6,%7}, {%8,%9}, {%0,%1,%2,%3};"
                 : "+f"(d[0]), "+f"(d[1]), "+f"(d[2]), "+f"(d[3])
                 : "r"(a[0]), "r"(a[1]), "r"(a[2]), "r"(a[3]), "r"(b[0]), "r"(b[1]));
}
__device__ __forceinline__ void cp16(uint32_t dst, const void* src, int sz) {
    asm volatile("cp.async.cg.shared.global [%0], [%1], 16, %2;"
                 :: "r"(dst), "l"(src), "r"(sz) : "memory");
}
__device__ __forceinline__ void cp_commit() {
    asm volatile("cp.async.commit_group;" ::: "memory");
}
__device__ __forceinline__ void split_bf(float v, __nv_bfloat16& h, __nv_bfloat16& l) {
    h = __float2bfloat16(v);
    l = __float2bfloat16(v - __bfloat162float(h));
}

// =====================================================================
// Warp-MMA split-bf16 GEMM: C[M,200](+ep) = (Ah+Al)[M,K] @ (Bh+Bl)^T
// B stored [200, ldb] bf16 row-major (pre-transposed). All K byte-strides
// must be multiples of 16.
// EP: 0 = f32 partial (Cbase + by*NROW*NCOL), 1 = relu(x+bias),
//     2 = GCNII combine, 3 = +bias, 4 = +bias+speaker
// =====================================================================
__device__ __forceinline__ void load_stage(
    uint32_t sb, const __nv_bfloat16* __restrict__ Ah, const __nv_bfloat16* __restrict__ Al,
    int lda, const __nv_bfloat16* __restrict__ Bh, const __nv_bfloat16* __restrict__ Bl,
    int ldb, int row0, int M, int kb, int ke, int tid)
{
    for (int g = tid; g < 2816; g += 256) {
        const __nv_bfloat16* srow;
        uint32_t toff;
        int r, c;
        bool rv;
        if (g < 1024) {
            int t = g >> 9, idx = g & 511;
            r = idx >> 2; c = idx & 3;
            srow = (t ? Al : Ah);
            toff = t ? SA_L : SA_H;
            rv = (row0 + r) < M;
            if (rv) srow += (size_t)(row0 + r) * lda;
        } else {
            int gb = g - 1024;
            int t = gb >= 896;
            int idx = t ? gb - 896 : gb;
            r = idx >> 2; c = idx & 3;
            srow = (t ? Bl : Bh);
            toff = t ? SB_L : SB_H;
            rv = r < NCOL;
            if (rv) srow += (size_t)r * ldb;
        }
        int k0 = kb + c * 8;
        int sz = 0;
        const void* sp = srow;
        if (rv) {
            int kv = (ke - k0) * 2;
            sz = kv >= 16 ? 16 : (kv > 0 ? kv : 0);
            if (sz > 0) sp = srow + k0;
        }
        uint32_t off = swz((uint32_t)(r * 64 + c * 16));
        cp16(sb + toff + off, sp, sz);
    }
}

template <int EP>
__global__ __launch_bounds__(256)
void mma_gemm(const __nv_bfloat16* __restrict__ Ah, const __nv_bfloat16* __restrict__ Al, int lda,
              const __nv_bfloat16* __restrict__ Bh, const __nv_bfloat16* __restrict__ Bl, int ldb,
              int M, int Ktot, int ksize,
              float* __restrict__ Cbase,
              const float* __restrict__ bias,
              const float* __restrict__ aux0, const float* __restrict__ aux1,
              float theta)
{
    extern __shared__ char dsm_raw[];
    const int tid  = threadIdx.x;
    const int wid  = tid >> 5;
    const int lane = tid & 31;
    const int wm   = wid >> 2;      // 0..1
    const int wn   = wid & 3;       // 0..3
    const int row0 = blockIdx.x * BMM;
    const int ks   = blockIdx.y * ksize;
    const int ke   = (ks + ksize < Ktot) ? (ks + ksize) : Ktot;
    float* Cout = (EP == 0) ? (Cbase + (size_t)blockIdx.y * (NROW * NCOL)) : Cbase;

    const uint32_t raw  = smem_u32(dsm_raw);
    const uint32_t base = (raw + 1023u) & ~1023u;

    float acc[4][7][4];
#pragma unroll
    for (int mt = 0; mt < 4; mt++)
#pragma unroll
        for (int nt = 0; nt < 7; nt++)
#pragma unroll
            for (int q = 0; q < 4; q++) acc[mt][nt][q] = 0.0f;

    const int nck = (ke - ks + 31) >> 5;

    int issued = 0;
    for (; issued < nck && issued < NST - 1; issued++) {
        load_stage(base + issued * STAGE, Ah, Al, lda, Bh, Bl, ldb,
                   row0, M, ks + issued * 32, ke, tid);
        cp_commit();
    }

    for (int i = 0; i < nck; i++) {
        if (nck - i >= 2) asm volatile("cp.async.wait_group 1;" ::: "memory");
        else              asm volatile("cp.async.wait_group 0;" ::: "memory");
        __syncthreads();
        if (issued < nck) {
            load_stage(base + (uint32_t)(issued % NST) * STAGE, Ah, Al, lda, Bh, Bl, ldb,
                       row0, M, ks + issued * 32, ke, tid);
            cp_commit();
            issued++;
        }

        const uint32_t sb  = base + (uint32_t)(i % NST) * STAGE;
        const uint32_t aHu = sb + SA_H, aLu = sb + SA_L;
        const uint32_t bHu = sb + SB_H, bLu = sb + SB_L;

#pragma unroll
        for (int ksub = 0; ksub < 2; ksub++) {
            uint32_t ah[4][4], al[4][4];
#pragma unroll
            for (int mt = 0; mt < 4; mt++) {
                int r  = wm * 64 + mt * 16 + (lane & 15);
                int ch = 2 * ksub + (lane >> 4);
                uint32_t off = swz((uint32_t)(r * 64 + ch * 16));
                ldsm4(ah[mt], aHu + off);
                ldsm4(al[mt], aLu + off);
            }
#pragma unroll
            for (int nt = 0; nt < 7; nt++) {
                int rb = wn * 56 + nt * 8 + (lane & 7);
                int cb = 2 * ksub + ((lane >> 3) & 1);
                uint32_t off = swz((uint32_t)(rb * 64 + cb * 16));
                uint32_t bh[2], bl[2];
                ldsm2(bh, bHu + off);
                ldsm2(bl, bLu + off);
#pragma unroll
                for (int mt = 0; mt < 4; mt++) {
                    mma16816(acc[mt][nt], ah[mt], bh);
                    mma16816(acc[mt][nt], ah[mt], bl);
                    mma16816(acc[mt][nt], al[mt], bh);
                }
            }
        }
    }

    // ---------------- epilogue ----------------
#pragma unroll
    for (int mt = 0; mt < 4; mt++) {
#pragma unroll
        for (int hf = 0; hf < 2; hf++) {
            const int r = row0 + wm * 64 + mt * 16 + (lane >> 2) + 8 * hf;
            if (r >= M) continue;
            int spk = 0;
            if (EP == 4) {
                int bI = r / 100, tI = r % 100;
                const float* q = aux0 + ((size_t)tI * 20 + bI) * 2;
                spk = (q[1] > q[0]) ? 1 : 0;
            }
#pragma unroll
            for (int nt = 0; nt < 7; nt++) {
                const int c = wn * 56 + nt * 8 + (lane & 3) * 2;
                if (c >= NCOL) continue;
                float vx = acc[mt][nt][2 * hf];
                float vy = acc[mt][nt][2 * hf + 1];
                if (EP == 1) {
                    vx = fmaxf(vx + bias[c], 0.0f);
                    vy = fmaxf(vy + bias[c + 1], 0.0f);
                } else if (EP == 2) {
                    float2 hiv = *(const float2*)&aux0[(size_t)r * NCOL + c];
                    float2 h0v = *(const float2*)&aux1[(size_t)r * NCOL + c];
                    float rx = 0.9f * hiv.x + 0.1f * h0v.x;
                    float ry = 0.9f * hiv.y + 0.1f * h0v.y;
                    vx = fmaxf(theta * vx + (1.0f - theta) * rx, 0.0f);
                    vy = fmaxf(theta * vy + (1.0f - theta) * ry, 0.0f);
                } else if (EP == 3) {
                    vx += bias[c];
                    vy += bias[c + 1];
                } else if (EP == 4) {
                    vx += bias[c]     + aux1[spk * NCOL + c];
                    vy += bias[c + 1] + aux1[spk * NCOL + c + 1];
                }
                float2 o; o.x = vx; o.y = vy;
                *(float2*)&Cout[(size_t)r * NCOL + c] = o;
            }
        }
    }
}

// =====================================================================
// conversion / assembly helpers
// =====================================================================
__global__ void convert_split4(const float* __restrict__ src, int n4,
                               __nv_bfloat16* __restrict__ dh,
                               __nv_bfloat16* __restrict__ dl)
{
    int i = blockIdx.x * blockDim.x + threadIdx.x;
    if (i < n4) {
        float4 v = ((const float4*)src)[i];
        __nv_bfloat16 h0, l0, h1, l1, h2, l2, h3, l3;
        split_bf(v.x, h0, l0); split_bf(v.y, h1, l1);
        split_bf(v.z, h2, l2); split_bf(v.w, h3, l3);
        __nv_bfloat162* H = (__nv_bfloat162*)dh;
        __nv_bfloat162* L = (__nv_bfloat162*)dl;
        H[2 * i]     = __nv_bfloat162(h0, h1);
        H[2 * i + 1] = __nv_bfloat162(h2, h3);
        L[2 * i]     = __nv_bfloat162(l0, l1);
        L[2 * i + 1] = __nv_bfloat162(l2, l3);
    }
}

// src [R][C] f32 -> dst [R][Cp] split bf16, zero-padded cols
__global__ void padsplit(const float* __restrict__ src, int R, int C, int Cp,
                         __nv_bfloat16* __restrict__ dh, __nv_bfloat16* __restrict__ dl)
{
    int i = blockIdx.x * blockDim.x + threadIdx.x;
    if (i < R * Cp) {
        int r = i / Cp, c = i % Cp;
        float v = (c < C) ? src[(size_t)r * C + c] : 0.0f;
        __nv_bfloat16 h, l;
        split_bf(v, h, l);
        dh[i] = h; dl[i] = l;
    }
}

// dst[C][Rp] (split bf16, zero-padded rows) = transpose of src[R][C] (f32)
__global__ void tsplit(const float* __restrict__ src, int R, int C, int Rp,
                       __nv_bfloat16* __restrict__ dh, __nv_bfloat16* __restrict__ dl)
{
    __shared__ float t[32][33];
    int r = blockIdx.x * 32 + threadIdx.y;
    int c = blockIdx.y * 32 + threadIdx.x;
    if (r < R && c < C) t[threadIdx.y][threadIdx.x] = src[(size_t)r * C + c];
    __syncthreads();
    int rr = blockIdx.x * 32 + threadIdx.x;
    int cc = blockIdx.y * 32 + threadIdx.y;
    if (rr < Rp && cc < C) {
        float v = (rr < R) ? t[threadIdx.x][threadIdx.y] : 0.0f;
        __nv_bfloat16 h, l;
        split_bf(v, h, l);
        dh[(size_t)cc * Rp + rr] = h;
        dl[(size_t)cc * Rp + rr] = l;
    }
}

// hi = sum of 3 partials; also write split(hi) into left half of S
__global__ void reduce_support() {
    int i = blockIdx.x * blockDim.x + threadIdx.x;
    const int S = NROW * NCOL;
    if (i < S) {
        float s = g_part[i] + g_part[i + S] + g_part[i + 2 * S];
        g_hi[i] = s;
        int r = i / NCOL, c = i % NCOL;
        __nv_bfloat16 h, l;
        split_bf(s, h, l);
        g_Sh[(size_t)r * 400 + c] = h;
        g_Sl[(size_t)r * 400 + c] = l;
    }
}

// right half of S = split(h0)  (constant across layers)
__global__ void s_right() {
    int i = blockIdx.x * blockDim.x + threadIdx.x;
    if (i < NROW * NCOL) {
        int r = i / NCOL, c = i % NCOL;
        __nv_bfloat16 h, l;
        split_bf(g_h0[i], h, l);
        g_Sh[(size_t)r * 400 + NCOL + c] = h;
        g_Sl[(size_t)r * 400 + NCOL + c] = l;
    }
}

__global__ void assemble_kernel(float* __restrict__ out) {
    int idx = blockIdx.x * blockDim.x + threadIdx.x;
    if (idx < NUTT * 1200) {
        int i = idx / 1200;
        int c = idx % 1200;
        int m = c / 400;
        int j = c % 400;
        const float* src = (j < 200) ? g_x : g_h;
        out[idx] = src[(size_t)(m * NUTT + i) * NCOL + (j % NCOL)];
    }
}

// =====================================================================
extern "C" void kernel_launch(void* const* d_in, const int* in_sizes, int n_in,
                              void* d_out, int out_size)
{
    const float* a     = (const float*)d_in[0];
    const float* v     = (const float*)d_in[1];
    const float* l     = (const float*)d_in[2];
    const float* qmask = (const float*)d_in[3];
    const float* adj   = (const float*)d_in[4];
    const float* Wa    = (const float*)d_in[5];
    const float* ba    = (const float*)d_in[6];
    const float* Wv    = (const float*)d_in[7];
    const float* bv    = (const float*)d_in[8];
    const float* Wl    = (const float*)d_in[9];
    const float* bl    = (const float*)d_in[10];
    const float* spk   = (const float*)d_in[11];
    const float* W0    = (const float*)d_in[12];
    const float* b0    = (const float*)d_in[13];
    const float* convW = (const float*)d_in[14];
    float* out = (float*)d_out;

    float *gx, *gh0, *gh, *ghi, *gpart;
    __nv_bfloat16 *adjh, *adjl, *hTh, *hTl, *Sh, *Sl, *WTh, *WTl, *W0Th, *W0Tl, *xh, *xl;
    __nv_bfloat16 *ah_, *al_, *vh_, *vl_, *lh_, *ll_;
    __nv_bfloat16 *WaTh, *WaTl, *WvTh, *WvTl, *WlTh, *WlTl;
    cudaGetSymbolAddress((void**)&gx,    g_x);
    cudaGetSymbolAddress((void**)&gh0,   g_h0);
    cudaGetSymbolAddress((void**)&gh,    g_h);
    cudaGetSymbolAddress((void**)&ghi,   g_hi);
    cudaGetSymbolAddress((void**)&gpart, g_part);
    cudaGetSymbolAddress((void**)&adjh,  g_adjh);
    cudaGetSymbolAddress((void**)&adjl,  g_adjl);
    cudaGetSymbolAddress((void**)&hTh,   g_hTh);
    cudaGetSymbolAddress((void**)&hTl,   g_hTl);
    cudaGetSymbolAddress((void**)&Sh,    g_Sh);
    cudaGetSymbolAddress((void**)&Sl,    g_Sl);
    cudaGetSymbolAddress((void**)&WTh,   g_WTh);
    cudaGetSymbolAddress((void**)&WTl,   g_WTl);
    cudaGetSymbolAddress((void**)&W0Th,  g_W0Th);
    cudaGetSymbolAddress((void**)&W0Tl,  g_W0Tl);
    cudaGetSymbolAddress((void**)&xh,    g_xh);
    cudaGetSymbolAddress((void**)&xl,    g_xl);
    cudaGetSymbolAddress((void**)&ah_,   g_ah_);
    cudaGetSymbolAddress((void**)&al_,   g_al_);
    cudaGetSymbolAddress((void**)&vh_,   g_vh_);
    cudaGetSymbolAddress((void**)&vl_,   g_vl_);
    cudaGetSymbolAddress((void**)&lh_,   g_lh_);
    cudaGetSymbolAddress((void**)&ll_,   g_ll_);
    cudaGetSymbolAddress((void**)&WaTh,  g_WaTh);
    cudaGetSymbolAddress((void**)&WaTl,  g_WaTl);
    cudaGetSymbolAddress((void**)&WvTh,  g_WvTh);
    cudaGetSymbolAddress((void**)&WvTl,  g_WvTl);
    cudaGetSymbolAddress((void**)&WlTh,  g_WlTh);
    cudaGetSymbolAddress((void**)&WlTl,  g_WlTl);

    cudaFuncSetAttribute(mma_gemm<0>, cudaFuncAttributeMaxDynamicSharedMemorySize, DSMEM);
    cudaFuncSetAttribute(mma_gemm<1>, cudaFuncAttributeMaxDynamicSharedMemorySize, DSMEM);
    cudaFuncSetAttribute(mma_gemm<2>, cudaFuncAttributeMaxDynamicSharedMemorySize, DSMEM);
    cudaFuncSetAttribute(mma_gemm<3>, cudaFuncAttributeMaxDynamicSharedMemorySize, DSMEM);
    cudaFuncSetAttribute(mma_gemm<4>, cudaFuncAttributeMaxDynamicSharedMemorySize, DSMEM);

    // ---- one-time conversions ----
    convert_split4<<<(NROW * NROW / 4 + 255) / 256, 256>>>(adj, NROW * NROW / 4, adjh, adjl);
    padsplit<<<(2000 * 304 + 255) / 256, 256>>>(a, 2000, 300,  304,  ah_, al_);
    padsplit<<<(2000 * 352 + 255) / 256, 256>>>(v, 2000, 342,  352,  vh_, vl_);
    padsplit<<<(2000 * 1024 + 255) / 256, 256>>>(l, 2000, 1024, 1024, lh_, ll_);
    tsplit<<<dim3(10, 7), dim3(32, 32)>>>(Wa, 300,  NCOL, 304,  WaTh, WaTl);
    tsplit<<<dim3(11, 7), dim3(32, 32)>>>(Wv, 342,  NCOL, 352,  WvTh, WvTl);
    tsplit<<<dim3(32, 7), dim3(32, 32)>>>(Wl, 1024, NCOL, 1024, WlTh, WlTl);
    tsplit<<<dim3(7, 7),  dim3(32, 32)>>>(W0, NCOL, NCOL, NCOL, W0Th, W0Tl);

    // ---- modality projections -> g_x ----
    const int gProj = (NUTT + BMM - 1) / BMM;    // 16
    const int gFull = (NROW + BMM - 1) / BMM;    // 47
    mma_gemm<3><<<dim3(gProj, 1), 256, DSMEM>>>(ah_, al_, 304, WaTh, WaTl, 304,
        NUTT, 304, 304, gx, ba, nullptr, nullptr, 0.0f);
    mma_gemm<3><<<dim3(gProj, 1), 256, DSMEM>>>(vh_, vl_, 352, WvTh, WvTl, 352,
        NUTT, 352, 352, gx + (size_t)NUTT * NCOL, bv, nullptr, nullptr, 0.0f);
    mma_gemm<4><<<dim3(gProj, 1), 256, DSMEM>>>(lh_, ll_, 1024, WlTh, WlTl, 1024,
        NUTT, 1024, 1024, gx + (size_t)2 * NUTT * NCOL, bl, qmask, spk, 0.0f);

    // ---- h0 = relu(x @ W0 + b0) ----
    convert_split4<<<(NROW * NCOL / 4 + 255) / 256, 256>>>(gx, NROW * NCOL / 4, xh, xl);
    mma_gemm<1><<<dim3(gFull, 1), 256, DSMEM>>>(xh, xl, NCOL, W0Th, W0Tl, NCOL,
        NROW, NCOL, NCOL, gh0, b0, nullptr, nullptr, 0.0f);
    s_right<<<(NROW * NCOL + 255) / 256, 256>>>();

    // ---- GCNII layers ----
    for (int lay = 0; lay < NLAY; lay++) {
        float theta = logf(0.5f / (float)(lay + 1) + 1.0f);
        const float* h_in = (lay == 0) ? gh0 : gh;

        tsplit<<<dim3(188, 7), dim3(32, 32)>>>(h_in, NROW, NCOL, NROW, hTh, hTl);

        mma_gemm<0><<<dim3(gFull, 3), 256, DSMEM>>>(adjh, adjl, NROW, hTh, hTl, NROW,
            NROW, NROW, 2000, gpart, nullptr, nullptr, nullptr, 0.0f);
        reduce_support<<<(NROW * NCOL + 255) / 256, 256>>>();

        const float* W = convW + (size_t)lay * 2 * NCOL * NCOL;
        tsplit<<<dim3(13, 7), dim3(32, 32)>>>(W, 2 * NCOL, NCOL, 2 * NCOL, WTh, WTl);

        mma_gemm<2><<<dim3(gFull, 1), 256, DSMEM>>>(Sh, Sl, 2 * NCOL, WTh, WTl, 2 * NCOL,
            NROW, 2 * NCOL, 2 * NCOL, gh, nullptr, ghi, gh0, theta);
    }

    assemble_kernel<<<(NUTT * 1200 + 255) / 256, 256>>>(out);
}

// round 6
// speedup vs baseline: 5.3763x; 1.1275x over previous
#include <cuda_runtime.h>
#include <cuda_bf16.h>
#include <cuda_fp16.h>
#include <math.h>
#include <stdint.h>

// ---------------- problem constants ----------------
#define NUTT   2000
#define NROW   6000
#define NCOL   200
#define NLAY   8

#define ADJ_SCALE   16384.0f
#define ADJ_ISCALE  (1.0f / 16384.0f)

// ---------------- split-bf16 MMA kernel geometry ----------------
#define BMM   128
#define BNN   224
#define NST   3
#define SA_H  0u
#define SA_L  8192u
#define SB_H  16384u
#define SB_L  30720u
#define STAGE 45056u
#define DSMEM (3*45056 + 1024)

// ---------------- fp16 single-pass kernel geometry ----------------
#define F_NST   4
#define F_SA    0u
#define F_SB    8192u
#define F_STAGE 22528u             // 8192 + 14336
#define F_DSMEM (4*22528 + 1024)   // 91136

// ---------------- scratch (device globals; no runtime alloc) ----------------
__device__ __align__(256) float g_x   [NROW * NCOL];
__device__ __align__(256) float g_h0  [NROW * NCOL];
__device__ __align__(256) float g_h   [NROW * NCOL];
__device__ __align__(256) float g_hi  [NROW * NCOL];
__device__ __align__(256) float g_part[3 * NROW * NCOL];

__device__ __align__(256) __half        g_adj16[NROW * NROW];
__device__ __align__(256) __half        g_hT16 [NCOL * NROW];
__device__ __align__(256) __nv_bfloat16 g_Sh  [NROW * 2 * NCOL];
__device__ __align__(256) __nv_bfloat16 g_Sl  [NROW * 2 * NCOL];
__device__ __align__(256) __nv_bfloat16 g_WTh [NCOL * 2 * NCOL];
__device__ __align__(256) __nv_bfloat16 g_WTl [NCOL * 2 * NCOL];
__device__ __align__(256) __nv_bfloat16 g_W0Th[NCOL * NCOL];
__device__ __align__(256) __nv_bfloat16 g_W0Tl[NCOL * NCOL];
__device__ __align__(256) __nv_bfloat16 g_xh  [NROW * NCOL];
__device__ __align__(256) __nv_bfloat16 g_xl  [NROW * NCOL];

__device__ __align__(256) __nv_bfloat16 g_ah_ [2000 * 304];
__device__ __align__(256) __nv_bfloat16 g_al_ [2000 * 304];
__device__ __align__(256) __nv_bfloat16 g_vh_ [2000 * 352];
__device__ __align__(256) __nv_bfloat16 g_vl_ [2000 * 352];
__device__ __align__(256) __nv_bfloat16 g_lh_ [2000 * 1024];
__device__ __align__(256) __nv_bfloat16 g_ll_ [2000 * 1024];
__device__ __align__(256) __nv_bfloat16 g_WaTh[NCOL * 304];
__device__ __align__(256) __nv_bfloat16 g_WaTl[NCOL * 304];
__device__ __align__(256) __nv_bfloat16 g_WvTh[NCOL * 352];
__device__ __align__(256) __nv_bfloat16 g_WvTl[NCOL * 352];
__device__ __align__(256) __nv_bfloat16 g_WlTh[NCOL * 1024];
__device__ __align__(256) __nv_bfloat16 g_WlTl[NCOL * 1024];

// ---------------- helpers ----------------
__device__ __forceinline__ uint32_t smem_u32(const void* p) {
    uint32_t a;
    asm("{ .reg .u64 t; cvta.to.shared.u64 t, %1; cvt.u32.u64 %0, t; }" : "=r"(a) : "l"(p));
    return a;
}
__device__ __forceinline__ uint32_t swz(uint32_t off) {   // 64B-row swizzle
    return off ^ ((off >> 2) & 0x30u);
}
__device__ __forceinline__ void ldsm4(uint32_t* r, uint32_t a) {
    asm volatile("ldmatrix.sync.aligned.m8n8.x4.shared.b16 {%0,%1,%2,%3}, [%4];"
                 : "=r"(r[0]), "=r"(r[1]), "=r"(r[2]), "=r"(r[3]) : "r"(a));
}
__device__ __forceinline__ void ldsm2(uint32_t* r, uint32_t a) {
    asm volatile("ldmatrix.sync.aligned.m8n8.x2.shared.b16 {%0,%1}, [%2];"
                 : "=r"(r[0]), "=r"(r[1]) : "r"(a));
}
__device__ __forceinline__ void mma_bf(float* d, const uint32_t* a, const uint32_t* b) {
    asm volatile("mma.sync.aligned.m16n8k16.row.col.f32.bf16.bf16.f32 "
                 "{%0,%1,%2,%3}, {%4,%5,%6,%7}, {%8,%9}, {%0,%1,%2,%3};"
                 : "+f"(d[0]), "+f"(d[1]), "+f"(d[2]), "+f"(d[3])
                 : "r"(a[0]), "r"(a[1]), "r"(a[2]), "r"(a[3]), "r"(b[0]), "r"(b[1]));
}
__device__ __forceinline__ void mma_hf(float* d, const uint32_t* a, const uint32_t* b) {
    asm volatile("mma.sync.aligned.m16n8k16.row.col.f32.f16.f16.f32 "
                 "{%0,%1,%2,%3}, {%4,%5,%6,%7}, {%8,%9}, {%0,%1,%2,%3};"
                 : "+f"(d[0]), "+f"(d[1]), "+f"(d[2]), "+f"(d[3])
                 : "r"(a[0]), "r"(a[1]), "r"(a[2]), "r"(a[3]), "r"(b[0]), "r"(b[1]));
}
__device__ __forceinline__ void cp16(uint32_t dst, const void* src, int sz) {
    asm volatile("cp.async.cg.shared.global [%0], [%1], 16, %2;"
                 :: "r"(dst), "l"(src), "r"(sz) : "memory");
}
__device__ __forceinline__ void cp_commit() {
    asm volatile("cp.async.commit_group;" ::: "memory");
}
__device__ __forceinline__ void split_bf(float v, __nv_bfloat16& h, __nv_bfloat16& l) {
    h = __float2bfloat16(v);
    l = __float2bfloat16(v - __bfloat162float(h));
}

// =====================================================================
// fp16 single-pass GEMM: Cpart[M,200] = A16[M,K] @ B16[200,K]^T
// (adj path; output is a K-split partial buffer at Cbase + by*NROW*NCOL)
// =====================================================================
__device__ __forceinline__ void load_stage_f16(
    uint32_t sb, const __half* __restrict__ A, int lda,
    const __half* __restrict__ B, int ldb,
    int row0, int M, int kb, int ke, int tid)
{
    for (int g = tid; g < 1408; g += 256) {
        const __half* srow;
        uint32_t toff;
        int r, c;
        bool rv;
        if (g < 512) {
            r = g >> 2; c = g & 3;
            srow = A; toff = F_SA;
            rv = (row0 + r) < M;
            if (rv) srow += (size_t)(row0 + r) * lda;
        } else {
            int idx = g - 512;
            r = idx >> 2; c = idx & 3;
            srow = B; toff = F_SB;
            rv = r < NCOL;
            if (rv) srow += (size_t)r * ldb;
        }
        int k0 = kb + c * 8;
        int sz = 0;
        const void* sp = srow;
        if (rv) {
            int kv = (ke - k0) * 2;
            sz = kv >= 16 ? 16 : (kv > 0 ? kv : 0);
            if (sz > 0) sp = srow + k0;
        }
        uint32_t off = swz((uint32_t)(r * 64 + c * 16));
        cp16(sb + toff + off, sp, sz);
    }
}

__global__ __launch_bounds__(256)
void mma_f16(const __half* __restrict__ A, int lda,
             const __half* __restrict__ B, int ldb,
             int M, int Ktot, int ksize, float* __restrict__ Cbase)
{
    extern __shared__ char dsm_raw[];
    const int tid  = threadIdx.x;
    const int wid  = tid >> 5;
    const int lane = tid & 31;
    const int wm   = wid >> 2;
    const int wn   = wid & 3;
    const int row0 = blockIdx.x * BMM;
    const int ks   = blockIdx.y * ksize;
    const int ke   = (ks + ksize < Ktot) ? (ks + ksize) : Ktot;
    float* Cout = Cbase + (size_t)blockIdx.y * (NROW * NCOL);

    const uint32_t raw  = smem_u32(dsm_raw);
    const uint32_t base = (raw + 1023u) & ~1023u;

    float acc[4][7][4];
#pragma unroll
    for (int mt = 0; mt < 4; mt++)
#pragma unroll
        for (int nt = 0; nt < 7; nt++)
#pragma unroll
            for (int q = 0; q < 4; q++) acc[mt][nt][q] = 0.0f;

    const int nck = (ke - ks + 31) >> 5;

    int issued = 0;
    for (; issued < nck && issued < F_NST - 1; issued++) {
        load_stage_f16(base + issued * F_STAGE, A, lda, B, ldb,
                       row0, M, ks + issued * 32, ke, tid);
        cp_commit();
    }

    for (int i = 0; i < nck; i++) {
        int allow = nck - i - 1;
        if (allow > F_NST - 2) allow = F_NST - 2;
        if (allow >= 2)      asm volatile("cp.async.wait_group 2;" ::: "memory");
        else if (allow == 1) asm volatile("cp.async.wait_group 1;" ::: "memory");
        else                 asm volatile("cp.async.wait_group 0;" ::: "memory");
        __syncthreads();
        if (issued < nck) {
            load_stage_f16(base + (uint32_t)(issued % F_NST) * F_STAGE, A, lda, B, ldb,
                           row0, M, ks + issued * 32, ke, tid);
            cp_commit();
            issued++;
        }

        const uint32_t aB = base + (uint32_t)(i % F_NST) * F_STAGE + F_SA;
        const uint32_t bB = base + (uint32_t)(i % F_NST) * F_STAGE + F_SB;

#pragma unroll
        for (int ksub = 0; ksub < 2; ksub++) {
            uint32_t ah[4][4];
#pragma unroll
            for (int mt = 0; mt < 4; mt++) {
                int r  = wm * 64 + mt * 16 + (lane & 15);
                int ch = 2 * ksub + (lane >> 4);
                ldsm4(ah[mt], aB + swz((uint32_t)(r * 64 + ch * 16)));
            }
#pragma unroll
            for (int nt = 0; nt < 7; nt++) {
                int rb = wn * 56 + nt * 8 + (lane & 7);
                int cb = 2 * ksub + ((lane >> 3) & 1);
                uint32_t bb[2];
                ldsm2(bb, bB + swz((uint32_t)(rb * 64 + cb * 16)));
#pragma unroll
                for (int mt = 0; mt < 4; mt++) mma_hf(acc[mt][nt], ah[mt], bb);
            }
        }
    }

#pragma unroll
    for (int mt = 0; mt < 4; mt++)
#pragma unroll
        for (int hf = 0; hf < 2; hf++) {
            const int r = row0 + wm * 64 + mt * 16 + (lane >> 2) + 8 * hf;
            if (r >= M) continue;
#pragma unroll
            for (int nt = 0; nt < 7; nt++) {
                const int c = wn * 56 + nt * 8 + (lane & 3) * 2;
                if (c >= NCOL) continue;
                float2 o;
                o.x = acc[mt][nt][2 * hf];
                o.y = acc[mt][nt][2 * hf + 1];
                *(float2*)&Cout[(size_t)r * NCOL + c] = o;
            }
        }
}

// =====================================================================
// split-bf16 3-pass GEMM (small GEMMs). EP: 0 partial, 1 relu+bias,
// 3 +bias, 4 +bias+speaker
// =====================================================================
__device__ __forceinline__ void load_stage(
    uint32_t sb, const __nv_bfloat16* __restrict__ Ah, const __nv_bfloat16* __restrict__ Al,
    int lda, const __nv_bfloat16* __restrict__ Bh, const __nv_bfloat16* __restrict__ Bl,
    int ldb, int row0, int M, int kb, int ke, int tid)
{
    for (int g = tid; g < 2816; g += 256) {
        const __nv_bfloat16* srow;
        uint32_t toff;
        int r, c;
        bool rv;
        if (g < 1024) {
            int t = g >> 9, idx = g & 511;
            r = idx >> 2; c = idx & 3;
            srow = (t ? Al : Ah);
            toff = t ? SA_L : SA_H;
            rv = (row0 + r) < M;
            if (rv) srow += (size_t)(row0 + r) * lda;
        } else {
            int gb = g - 1024;
            int t = gb >= 896;
            int idx = t ? gb - 896 : gb;
            r = idx >> 2; c = idx & 3;
            srow = (t ? Bl : Bh);
            toff = t ? SB_L : SB_H;
            rv = r < NCOL;
            if (rv) srow += (size_t)r * ldb;
        }
        int k0 = kb + c * 8;
        int sz = 0;
        const void* sp = srow;
        if (rv) {
            int kv = (ke - k0) * 2;
            sz = kv >= 16 ? 16 : (kv > 0 ? kv : 0);
            if (sz > 0) sp = srow + k0;
        }
        uint32_t off = swz((uint32_t)(r * 64 + c * 16));
        cp16(sb + toff + off, sp, sz);
    }
}

template <int EP>
__global__ __launch_bounds__(256)
void mma_gemm(const __nv_bfloat16* __restrict__ Ah, const __nv_bfloat16* __restrict__ Al, int lda,
              const __nv_bfloat16* __restrict__ Bh, const __nv_bfloat16* __restrict__ Bl, int ldb,
              int M, int Ktot, int ksize,
              float* __restrict__ Cbase,
              const float* __restrict__ bias,
              const float* __restrict__ aux0, const float* __restrict__ aux1)
{
    extern __shared__ char dsm_raw[];
    const int tid  = threadIdx.x;
    const int wid  = tid >> 5;
    const int lane = tid & 31;
    const int wm   = wid >> 2;
    const int wn   = wid & 3;
    const int row0 = blockIdx.x * BMM;
    const int ks   = blockIdx.y * ksize;
    const int ke   = (ks + ksize < Ktot) ? (ks + ksize) : Ktot;
    float* Cout = (EP == 0) ? (Cbase + (size_t)blockIdx.y * (NROW * NCOL)) : Cbase;

    const uint32_t raw  = smem_u32(dsm_raw);
    const uint32_t base = (raw + 1023u) & ~1023u;

    float acc[4][7][4];
#pragma unroll
    for (int mt = 0; mt < 4; mt++)
#pragma unroll
        for (int nt = 0; nt < 7; nt++)
#pragma unroll
            for (int q = 0; q < 4; q++) acc[mt][nt][q] = 0.0f;

    const int nck = (ke - ks + 31) >> 5;

    int issued = 0;
    for (; issued < nck && issued < NST - 1; issued++) {
        load_stage(base + issued * STAGE, Ah, Al, lda, Bh, Bl, ldb,
                   row0, M, ks + issued * 32, ke, tid);
        cp_commit();
    }

    for (int i = 0; i < nck; i++) {
        if (nck - i >= 2) asm volatile("cp.async.wait_group 1;" ::: "memory");
        else              asm volatile("cp.async.wait_group 0;" ::: "memory");
        __syncthreads();
        if (issued < nck) {
            load_stage(base + (uint32_t)(issued % NST) * STAGE, Ah, Al, lda, Bh, Bl, ldb,
                       row0, M, ks + issued * 32, ke, tid);
            cp_commit();
            issued++;
        }

        const uint32_t sb  = base + (uint32_t)(i % NST) * STAGE;
        const uint32_t aHu = sb + SA_H, aLu = sb + SA_L;
        const uint32_t bHu = sb + SB_H, bLu = sb + SB_L;

#pragma unroll
        for (int ksub = 0; ksub < 2; ksub++) {
            uint32_t ah[4][4], al[4][4];
#pragma unroll
            for (int mt = 0; mt < 4; mt++) {
                int r  = wm * 64 + mt * 16 + (lane & 15);
                int ch = 2 * ksub + (lane >> 4);
                uint32_t off = swz((uint32_t)(r * 64 + ch * 16));
                ldsm4(ah[mt], aHu + off);
                ldsm4(al[mt], aLu + off);
            }
#pragma unroll
            for (int nt = 0; nt < 7; nt++) {
                int rb = wn * 56 + nt * 8 + (lane & 7);
                int cb = 2 * ksub + ((lane >> 3) & 1);
                uint32_t off = swz((uint32_t)(rb * 64 + cb * 16));
                uint32_t bh[2], bl[2];
                ldsm2(bh, bHu + off);
                ldsm2(bl, bLu + off);
#pragma unroll
                for (int mt = 0; mt < 4; mt++) {
                    mma_bf(acc[mt][nt], ah[mt], bh);
                    mma_bf(acc[mt][nt], ah[mt], bl);
                    mma_bf(acc[mt][nt], al[mt], bh);
                }
            }
        }
    }

#pragma unroll
    for (int mt = 0; mt < 4; mt++) {
#pragma unroll
        for (int hf = 0; hf < 2; hf++) {
            const int r = row0 + wm * 64 + mt * 16 + (lane >> 2) + 8 * hf;
            if (r >= M) continue;
            int spk = 0;
            if (EP == 4) {
                int bI = r / 100, tI = r % 100;
                const float* q = aux0 + ((size_t)tI * 20 + bI) * 2;
                spk = (q[1] > q[0]) ? 1 : 0;
            }
#pragma unroll
            for (int nt = 0; nt < 7; nt++) {
                const int c = wn * 56 + nt * 8 + (lane & 3) * 2;
                if (c >= NCOL) continue;
                float vx = acc[mt][nt][2 * hf];
                float vy = acc[mt][nt][2 * hf + 1];
                if (EP == 1) {
                    vx = fmaxf(vx + bias[c], 0.0f);
                    vy = fmaxf(vy + bias[c + 1], 0.0f);
                } else if (EP == 3) {
                    vx += bias[c];
                    vy += bias[c + 1];
                } else if (EP == 4) {
                    vx += bias[c]     + aux1[spk * NCOL + c];
                    vy += bias[c + 1] + aux1[spk * NCOL + c + 1];
                }
                float2 o; o.x = vx; o.y = vy;
                *(float2*)&Cout[(size_t)r * NCOL + c] = o;
            }
        }
    }
}

// =====================================================================
// elementwise / conversion kernels
// =====================================================================
__global__ void convert_adj_f16(const float* __restrict__ src, int n4,
                                __half* __restrict__ dst)
{
    int i = blockIdx.x * blockDim.x + threadIdx.x;
    if (i < n4) {
        float4 v = ((const float4*)src)[i];
        __half2* D = (__half2*)dst;
        D[2 * i]     = __floats2half2_rn(v.x * ADJ_SCALE, v.y * ADJ_SCALE);
        D[2 * i + 1] = __floats2half2_rn(v.z * ADJ_SCALE, v.w * ADJ_SCALE);
    }
}

__global__ void convert_split4(const float* __restrict__ src, int n4,
                               __nv_bfloat16* __restrict__ dh,
                               __nv_bfloat16* __restrict__ dl)
{
    int i = blockIdx.x * blockDim.x + threadIdx.x;
    if (i < n4) {
        float4 v = ((const float4*)src)[i];
        __nv_bfloat16 h0, l0, h1, l1, h2, l2, h3, l3;
        split_bf(v.x, h0, l0); split_bf(v.y, h1, l1);
        split_bf(v.z, h2, l2); split_bf(v.w, h3, l3);
        __nv_bfloat162* H = (__nv_bfloat162*)dh;
        __nv_bfloat162* L = (__nv_bfloat162*)dl;
        H[2 * i]     = __nv_bfloat162(h0, h1);
        H[2 * i + 1] = __nv_bfloat162(h2, h3);
        L[2 * i]     = __nv_bfloat162(l0, l1);
        L[2 * i + 1] = __nv_bfloat162(l2, l3);
    }
}

__global__ void padsplit(const float* __restrict__ src, int R, int C, int Cp,
                         __nv_bfloat16* __restrict__ dh, __nv_bfloat16* __restrict__ dl)
{
    int i = blockIdx.x * blockDim.x + threadIdx.x;
    if (i < R * Cp) {
        int r = i / Cp, c = i % Cp;
        float v = (c < C) ? src[(size_t)r * C + c] : 0.0f;
        __nv_bfloat16 h, l;
        split_bf(v, h, l);
        dh[i] = h; dl[i] = l;
    }
}

__global__ void tsplit(const float* __restrict__ src, int R, int C, int Rp,
                       __nv_bfloat16* __restrict__ dh, __nv_bfloat16* __restrict__ dl)
{
    __shared__ float t[32][33];
    int r = blockIdx.x * 32 + threadIdx.y;
    int c = blockIdx.y * 32 + threadIdx.x;
    if (r < R && c < C) t[threadIdx.y][threadIdx.x] = src[(size_t)r * C + c];
    __syncthreads();
    int rr = blockIdx.x * 32 + threadIdx.x;
    int cc = blockIdx.y * 32 + threadIdx.y;
    if (rr < Rp && cc < C) {
        float v = (rr < R) ? t[threadIdx.x][threadIdx.y] : 0.0f;
        __nv_bfloat16 h, l;
        split_bf(v, h, l);
        dh[(size_t)cc * Rp + rr] = h;
        dl[(size_t)cc * Rp + rr] = l;
    }
}

// transpose h0 [6000,200] f32 -> g_hT16 [200,6000] fp16
__global__ void t_f16(const float* __restrict__ src) {
    __shared__ float t[32][33];
    int r = blockIdx.x * 32 + threadIdx.y;
    int c = blockIdx.y * 32 + threadIdx.x;
    if (r < NROW && c < NCOL) t[threadIdx.y][threadIdx.x] = src[(size_t)r * NCOL + c];
    __syncthreads();
    int rr = blockIdx.x * 32 + threadIdx.x;
    int cc = blockIdx.y * 32 + threadIdx.y;
    if (rr < NROW && cc < NCOL)
        g_hT16[(size_t)cc * NROW + rr] = __float2half(t[threadIdx.x][threadIdx.y]);
}

// hi = scale_down(sum of 3 adj partials); write hi f32 + split into S left half
__global__ void reduce_support() {
    int i = blockIdx.x * blockDim.x + threadIdx.x;
    const int S = NROW * NCOL;
    if (i < S) {
        float s = (g_part[i] + g_part[i + S] + g_part[i + 2 * S]) * ADJ_ISCALE;
        g_hi[i] = s;
        int r = i / NCOL, c = i % NCOL;
        __nv_bfloat16 h, l;
        split_bf(s, h, l);
        g_Sh[(size_t)r * 400 + c] = h;
        g_Sl[(size_t)r * 400 + c] = l;
    }
}

// right half of S = split(h0)  (constant across layers)
__global__ void s_right() {
    int i = blockIdx.x * blockDim.x + threadIdx.x;
    if (i < NROW * NCOL) {
        int r = i / NCOL, c = i % NCOL;
        __nv_bfloat16 h, l;
        split_bf(g_h0[i], h, l);
        g_Sh[(size_t)r * 400 + NCOL + c] = h;
        g_Sl[(size_t)r * 400 + NCOL + c] = l;
    }
}

// sum 3 S@W partials + GCNII combine + relu -> g_h, and write g_hT16 transposed
__global__ void reduce_gcnii(float theta) {
    __shared__ float t[32][33];
    int r = blockIdx.x * 32 + threadIdx.y;
    int c = blockIdx.y * 32 + threadIdx.x;
    const int S = NROW * NCOL;
    float val = 0.0f;
    if (r < NROW && c < NCOL) {
        int i = r * NCOL + c;
        float sw = g_part[i] + g_part[i + S] + g_part[i + 2 * S];
        float rr = 0.9f * g_hi[i] + 0.1f * g_h0[i];
        val = fmaxf(theta * sw + (1.0f - theta) * rr, 0.0f);
        g_h[i] = val;
    }
    t[threadIdx.y][threadIdx.x] = val;
    __syncthreads();
    int rr2 = blockIdx.x * 32 + threadIdx.x;
    int cc = blockIdx.y * 32 + threadIdx.y;
    if (rr2 < NROW && cc < NCOL)
        g_hT16[(size_t)cc * NROW + rr2] = __float2half(t[threadIdx.x][threadIdx.y]);
}

__global__ void assemble_kernel(float* __restrict__ out) {
    int idx = blockIdx.x * blockDim.x + threadIdx.x;
    if (idx < NUTT * 1200) {
        int i = idx / 1200;
        int c = idx % 1200;
        int m = c / 400;
        int j = c % 400;
        const float* src = (j < 200) ? g_x : g_h;
        out[idx] = src[(size_t)(m * NUTT + i) * NCOL + (j % NCOL)];
    }
}

// =====================================================================
extern "C" void kernel_launch(void* const* d_in, const int* in_sizes, int n_in,
                              void* d_out, int out_size)
{
    const float* a     = (const float*)d_in[0];
    const float* v     = (const float*)d_in[1];
    const float* l     = (const float*)d_in[2];
    const float* qmask = (const float*)d_in[3];
    const float* adj   = (const float*)d_in[4];
    const float* Wa    = (const float*)d_in[5];
    const float* ba    = (const float*)d_in[6];
    const float* Wv    = (const float*)d_in[7];
    const float* bv    = (const float*)d_in[8];
    const float* Wl    = (const float*)d_in[9];
    const float* bl    = (const float*)d_in[10];
    const float* spk   = (const float*)d_in[11];
    const float* W0    = (const float*)d_in[12];
    const float* b0    = (const float*)d_in[13];
    const float* convW = (const float*)d_in[14];
    float* out = (float*)d_out;

    float *gx, *gh0, *gh, *gpart;
    __half *adj16, *hT16;
    __nv_bfloat16 *Sh, *Sl, *WTh, *WTl, *W0Th, *W0Tl, *xh, *xl;
    __nv_bfloat16 *ah_, *al_, *vh_, *vl_, *lh_, *ll_;
    __nv_bfloat16 *WaTh, *WaTl, *WvTh, *WvTl, *WlTh, *WlTl;
    cudaGetSymbolAddress((void**)&gx,    g_x);
    cudaGetSymbolAddress((void**)&gh0,   g_h0);
    cudaGetSymbolAddress((void**)&gh,    g_h);
    cudaGetSymbolAddress((void**)&gpart, g_part);
    cudaGetSymbolAddress((void**)&adj16, g_adj16);
    cudaGetSymbolAddress((void**)&hT16,  g_hT16);
    cudaGetSymbolAddress((void**)&Sh,    g_Sh);
    cudaGetSymbolAddress((void**)&Sl,    g_Sl);
    cudaGetSymbolAddress((void**)&WTh,   g_WTh);
    cudaGetSymbolAddress((void**)&WTl,   g_WTl);
    cudaGetSymbolAddress((void**)&W0Th,  g_W0Th);
    cudaGetSymbolAddress((void**)&W0Tl,  g_W0Tl);
    cudaGetSymbolAddress((void**)&xh,    g_xh);
    cudaGetSymbolAddress((void**)&xl,    g_xl);
    cudaGetSymbolAddress((void**)&ah_,   g_ah_);
    cudaGetSymbolAddress((void**)&al_,   g_al_);
    cudaGetSymbolAddress((void**)&vh_,   g_vh_);
    cudaGetSymbolAddress((void**)&vl_,   g_vl_);
    cudaGetSymbolAddress((void**)&lh_,   g_lh_);
    cudaGetSymbolAddress((void**)&ll_,   g_ll_);
    cudaGetSymbolAddress((void**)&WaTh,  g_WaTh);
    cudaGetSymbolAddress((void**)&WaTl,  g_WaTl);
    cudaGetSymbolAddress((void**)&WvTh,  g_WvTh);
    cudaGetSymbolAddress((void**)&WvTl,  g_WvTl);
    cudaGetSymbolAddress((void**)&WlTh,  g_WlTh);
    cudaGetSymbolAddress((void**)&WlTl,  g_WlTl);

    cudaFuncSetAttribute(mma_f16,     cudaFuncAttributeMaxDynamicSharedMemorySize, F_DSMEM);
    cudaFuncSetAttribute(mma_gemm<0>, cudaFuncAttributeMaxDynamicSharedMemorySize, DSMEM);
    cudaFuncSetAttribute(mma_gemm<1>, cudaFuncAttributeMaxDynamicSharedMemorySize, DSMEM);
    cudaFuncSetAttribute(mma_gemm<3>, cudaFuncAttributeMaxDynamicSharedMemorySize, DSMEM);
    cudaFuncSetAttribute(mma_gemm<4>, cudaFuncAttributeMaxDynamicSharedMemorySize, DSMEM);

    // ---- one-time conversions ----
    convert_adj_f16<<<(NROW * NROW / 4 + 255) / 256, 256>>>(adj, NROW * NROW / 4, adj16);
    padsplit<<<(2000 * 304 + 255) / 256, 256>>>(a, 2000, 300,  304,  ah_, al_);
    padsplit<<<(2000 * 352 + 255) / 256, 256>>>(v, 2000, 342,  352,  vh_, vl_);
    padsplit<<<(2000 * 1024 + 255) / 256, 256>>>(l, 2000, 1024, 1024, lh_, ll_);
    tsplit<<<dim3(10, 7), dim3(32, 32)>>>(Wa, 300,  NCOL, 304,  WaTh, WaTl);
    tsplit<<<dim3(11, 7), dim3(32, 32)>>>(Wv, 342,  NCOL, 352,  WvTh, WvTl);
    tsplit<<<dim3(32, 7), dim3(32, 32)>>>(Wl, 1024, NCOL, 1024, WlTh, WlTl);
    tsplit<<<dim3(7, 7),  dim3(32, 32)>>>(W0, NCOL, NCOL, NCOL, W0Th, W0Tl);

    // ---- modality projections -> g_x ----
    const int gProj = (NUTT + BMM - 1) / BMM;    // 16
    const int gFull = (NROW + BMM - 1) / BMM;    // 47
    mma_gemm<3><<<dim3(gProj, 1), 256, DSMEM>>>(ah_, al_, 304, WaTh, WaTl, 304,
        NUTT, 304, 304, gx, ba, nullptr, nullptr);
    mma_gemm<3><<<dim3(gProj, 1), 256, DSMEM>>>(vh_, vl_, 352, WvTh, WvTl, 352,
        NUTT, 352, 352, gx + (size_t)NUTT * NCOL, bv, nullptr, nullptr);
    mma_gemm<4><<<dim3(gProj, 1), 256, DSMEM>>>(lh_, ll_, 1024, WlTh, WlTl, 1024,
        NUTT, 1024, 1024, gx + (size_t)2 * NUTT * NCOL, bl, qmask, spk);

    // ---- h0 = relu(x @ W0 + b0) ----
    convert_split4<<<(NROW * NCOL / 4 + 255) / 256, 256>>>(gx, NROW * NCOL / 4, xh, xl);
    mma_gemm<1><<<dim3(gFull, 1), 256, DSMEM>>>(xh, xl, NCOL, W0Th, W0Tl, NCOL,
        NROW, NCOL, NCOL, gh0, b0, nullptr, nullptr);
    s_right<<<(NROW * NCOL + 255) / 256, 256>>>();
    t_f16<<<dim3(188, 7), dim3(32, 32)>>>(gh0);

    // ---- GCNII layers ----
    for (int lay = 0; lay < NLAY; lay++) {
        float theta = logf(0.5f / (float)(lay + 1) + 1.0f);

        // hi partials = (adj*2^14) @ h   (fp16 single-pass, K split 3)
        mma_f16<<<dim3(gFull, 3), 256, F_DSMEM>>>(adj16, NROW, hT16, NROW,
            NROW, NROW, 2000, gpart);
        reduce_support<<<(NROW * NCOL + 255) / 256, 256>>>();

        const float* W = convW + (size_t)lay * 2 * NCOL * NCOL;
        tsplit<<<dim3(13, 7), dim3(32, 32)>>>(W, 2 * NCOL, NCOL, 2 * NCOL, WTh, WTl);

        // S@W partials (split-bf16, K=400 split 3: 144/144/112)
        mma_gemm<0><<<dim3(gFull, 3), 256, DSMEM>>>(Sh, Sl, 2 * NCOL, WTh, WTl, 2 * NCOL,
            NROW, 2 * NCOL, 144, gpart, nullptr, nullptr, nullptr);

        // combine + relu -> g_h ; also write h^T fp16 for next layer
        reduce_gcnii<<<dim3(188, 7), dim3(32, 32)>>>(theta);
    }

    assemble_kernel<<<(NUTT * 1200 + 255) / 256, 256>>>(out);
}

// round 7
// speedup vs baseline: 8.6053x; 1.6006x over previous
#include <cuda_runtime.h>
#include <cuda_bf16.h>
#include <cuda_fp16.h>
#include <math.h>
#include <stdint.h>

// ---------------- problem constants ----------------
#define NUTT   2000
#define NROW   6000
#define NCOL   200
#define NLAY   8
#define SFULL  (NROW * NCOL)

#define ADJ_SCALE   16384.0f
#define ADJ_ISCALE  (1.0f / 16384.0f)

// ---------------- split-bf16 MMA kernel geometry ----------------
#define BMM   128
#define NST   3
#define SA_H  0u
#define SA_L  8192u
#define SB_H  16384u
#define SB_L  30720u
#define STAGE 45056u
#define DSMEM (3*45056 + 1024)

// ---------------- fp16 single-pass kernel geometry ----------------
#define F_NST   4
#define F_SA    0u
#define F_SB    8192u
#define F_STAGE 22528u
#define F_DSMEM (4*22528 + 1024)

// ---------------- scratch ----------------
__device__ __align__(256) float g_x   [SFULL];
__device__ __align__(256) float g_h0  [SFULL];
__device__ __align__(256) float g_h   [SFULL];
__device__ __align__(256) float g_hi  [SFULL];
__device__ __align__(256) float g_part[3 * SFULL];

__device__ __align__(256) __half        g_adj16[NROW * NROW];
__device__ __align__(256) __half        g_hT16 [NCOL * NROW];
__device__ __align__(256) __nv_bfloat16 g_hih  [SFULL];
__device__ __align__(256) __nv_bfloat16 g_hil  [SFULL];
__device__ __align__(256) __nv_bfloat16 g_h0h  [SFULL];
__device__ __align__(256) __nv_bfloat16 g_h0l  [SFULL];
__device__ __align__(256) __nv_bfloat16 g_WTh8 [NLAY * NCOL * 2 * NCOL];
__device__ __align__(256) __nv_bfloat16 g_WTl8 [NLAY * NCOL * 2 * NCOL];
__device__ __align__(256) __nv_bfloat16 g_W0Th [NCOL * NCOL];
__device__ __align__(256) __nv_bfloat16 g_W0Tl [NCOL * NCOL];
__device__ __align__(256) __nv_bfloat16 g_xh   [SFULL];
__device__ __align__(256) __nv_bfloat16 g_xl   [SFULL];

__device__ __align__(256) __nv_bfloat16 g_ah_ [2000 * 304];
__device__ __align__(256) __nv_bfloat16 g_al_ [2000 * 304];
__device__ __align__(256) __nv_bfloat16 g_vh_ [2000 * 352];
__device__ __align__(256) __nv_bfloat16 g_vl_ [2000 * 352];
__device__ __align__(256) __nv_bfloat16 g_lh_ [2000 * 1024];
__device__ __align__(256) __nv_bfloat16 g_ll_ [2000 * 1024];
__device__ __align__(256) __nv_bfloat16 g_WaTh[NCOL * 304];
__device__ __align__(256) __nv_bfloat16 g_WaTl[NCOL * 304];
__device__ __align__(256) __nv_bfloat16 g_WvTh[NCOL * 352];
__device__ __align__(256) __nv_bfloat16 g_WvTl[NCOL * 352];
__device__ __align__(256) __nv_bfloat16 g_WlTh[NCOL * 1024];
__device__ __align__(256) __nv_bfloat16 g_WlTl[NCOL * 1024];

// ---------------- helpers ----------------
__device__ __forceinline__ uint32_t smem_u32(const void* p) {
    uint32_t a;
    asm("{ .reg .u64 t; cvta.to.shared.u64 t, %1; cvt.u32.u64 %0, t; }" : "=r"(a) : "l"(p));
    return a;
}
// 64B-row swizzle: XOR chunk bits[4:5] with row bits (off bits [7:8]) ->
// phase = (row>>1)&3 : conflict-free for 8-row ldmatrix reads and
// 8-row x 4-chunk cp.async warp stores.
__device__ __forceinline__ uint32_t swz(uint32_t off) {
    return off ^ ((off >> 3) & 0x30u);
}
__device__ __forceinline__ void ldsm4(uint32_t* r, uint32_t a) {
    asm volatile("ldmatrix.sync.aligned.m8n8.x4.shared.b16 {%0,%1,%2,%3}, [%4];"
                 : "=r"(r[0]), "=r"(r[1]), "=r"(r[2]), "=r"(r[3]) : "r"(a));
}
__device__ __forceinline__ void ldsm2(uint32_t* r, uint32_t a) {
    asm volatile("ldmatrix.sync.aligned.m8n8.x2.shared.b16 {%0,%1}, [%2];"
                 : "=r"(r[0]), "=r"(r[1]) : "r"(a));
}
__device__ __forceinline__ void mma_bf(float* d, const uint32_t* a, const uint32_t* b) {
    asm volatile("mma.sync.aligned.m16n8k16.row.col.f32.bf16.bf16.f32 "
                 "{%0,%1,%2,%3}, {%4,%5,%6,%7}, {%8,%9}, {%0,%1,%2,%3};"
                 : "+f"(d[0]), "+f"(d[1]), "+f"(d[2]), "+f"(d[3])
                 : "r"(a[0]), "r"(a[1]), "r"(a[2]), "r"(a[3]), "r"(b[0]), "r"(b[1]));
}
__device__ __forceinline__ void mma_hf(float* d, const uint32_t* a, const uint32_t* b) {
    asm volatile("mma.sync.aligned.m16n8k16.row.col.f32.f16.f16.f32 "
                 "{%0,%1,%2,%3}, {%4,%5,%6,%7}, {%8,%9}, {%0,%1,%2,%3};"
                 : "+f"(d[0]), "+f"(d[1]), "+f"(d[2]), "+f"(d[3])
                 : "r"(a[0]), "r"(a[1]), "r"(a[2]), "r"(a[3]), "r"(b[0]), "r"(b[1]));
}
__device__ __forceinline__ void cp16(uint32_t dst, const void* src, int sz) {
    asm volatile("cp.async.cg.shared.global [%0], [%1], 16, %2;"
                 :: "r"(dst), "l"(src), "r"(sz) : "memory");
}
__device__ __forceinline__ void cp_commit() {
    asm volatile("cp.async.commit_group;" ::: "memory");
}
__device__ __forceinline__ void split_bf(float v, __nv_bfloat16& h, __nv_bfloat16& l) {
    h = __float2bfloat16(v);
    l = __float2bfloat16(v - __bfloat162float(h));
}

// =====================================================================
// fp16 single-pass GEMM (adj path)
// =====================================================================
__device__ __forceinline__ void load_stage_f16(
    uint32_t sb, const __half* __restrict__ A, int lda,
    const __half* __restrict__ B, int ldb,
    int row0, int M, int kb, int ke, int tid)
{
    for (int g = tid; g < 1408; g += 256) {
        const __half* srow;
        uint32_t toff;
        int r, c;
        bool rv;
        if (g < 512) {
            r = g >> 2; c = g & 3;
            srow = A; toff = F_SA;
            rv = (row0 + r) < M;
            if (rv) srow += (size_t)(row0 + r) * lda;
        } else {
            int idx = g - 512;
            r = idx >> 2; c = idx & 3;
            srow = B; toff = F_SB;
            rv = r < NCOL;
            if (rv) srow += (size_t)r * ldb;
        }
        int k0 = kb + c * 8;
        int sz = 0;
        const void* sp = srow;
        if (rv) {
            int kv = (ke - k0) * 2;
            sz = kv >= 16 ? 16 : (kv > 0 ? kv : 0);
            if (sz > 0) sp = srow + k0;
        }
        cp16(sb + toff + swz((uint32_t)(r * 64 + c * 16)), sp, sz);
    }
}

__global__ __launch_bounds__(256)
void mma_f16(const __half* __restrict__ A, int lda,
             const __half* __restrict__ B, int ldb,
             int M, int Ktot, int ksize, float* __restrict__ Cbase)
{
    extern __shared__ char dsm_raw[];
    const int tid  = threadIdx.x;
    const int wid  = tid >> 5;
    const int lane = tid & 31;
    const int wm   = wid >> 2;
    const int wn   = wid & 3;
    const int row0 = blockIdx.x * BMM;
    const int ks   = blockIdx.y * ksize;
    const int ke   = (ks + ksize < Ktot) ? (ks + ksize) : Ktot;
    float* Cout = Cbase + (size_t)blockIdx.y * SFULL;

    const uint32_t base = (smem_u32(dsm_raw) + 1023u) & ~1023u;

    float acc[4][7][4];
#pragma unroll
    for (int mt = 0; mt < 4; mt++)
#pragma unroll
        for (int nt = 0; nt < 7; nt++)
#pragma unroll
            for (int q = 0; q < 4; q++) acc[mt][nt][q] = 0.0f;

    const int nck = (ke - ks + 31) >> 5;

    int issued = 0;
    for (; issued < nck && issued < F_NST - 1; issued++) {
        load_stage_f16(base + issued * F_STAGE, A, lda, B, ldb,
                       row0, M, ks + issued * 32, ke, tid);
        cp_commit();
    }

    for (int i = 0; i < nck; i++) {
        int allow = nck - i - 1;
        if (allow > F_NST - 2) allow = F_NST - 2;
        if (allow >= 2)      asm volatile("cp.async.wait_group 2;" ::: "memory");
        else if (allow == 1) asm volatile("cp.async.wait_group 1;" ::: "memory");
        else                 asm volatile("cp.async.wait_group 0;" ::: "memory");
        __syncthreads();
        if (issued < nck) {
            load_stage_f16(base + (uint32_t)(issued % F_NST) * F_STAGE, A, lda, B, ldb,
                           row0, M, ks + issued * 32, ke, tid);
            cp_commit();
            issued++;
        }

        const uint32_t aB = base + (uint32_t)(i % F_NST) * F_STAGE + F_SA;
        const uint32_t bB = base + (uint32_t)(i % F_NST) * F_STAGE + F_SB;

#pragma unroll
        for (int ksub = 0; ksub < 2; ksub++) {
            uint32_t ah[4][4];
#pragma unroll
            for (int mt = 0; mt < 4; mt++) {
                int r  = wm * 64 + mt * 16 + (lane & 15);
                int ch = 2 * ksub + (lane >> 4);
                ldsm4(ah[mt], aB + swz((uint32_t)(r * 64 + ch * 16)));
            }
#pragma unroll
            for (int nt = 0; nt < 7; nt++) {
                int rb = wn * 56 + nt * 8 + (lane & 7);
                int cb = 2 * ksub + ((lane >> 3) & 1);
                uint32_t bb[2];
                ldsm2(bb, bB + swz((uint32_t)(rb * 64 + cb * 16)));
#pragma unroll
                for (int mt = 0; mt < 4; mt++) mma_hf(acc[mt][nt], ah[mt], bb);
            }
        }
    }

#pragma unroll
    for (int mt = 0; mt < 4; mt++)
#pragma unroll
        for (int hf = 0; hf < 2; hf++) {
            const int r = row0 + wm * 64 + mt * 16 + (lane >> 2) + 8 * hf;
            if (r >= M) continue;
#pragma unroll
            for (int nt = 0; nt < 7; nt++) {
                const int c = wn * 56 + nt * 8 + (lane & 3) * 2;
                if (c >= NCOL) continue;
                float2 o;
                o.x = acc[mt][nt][2 * hf];
                o.y = acc[mt][nt][2 * hf + 1];
                *(float2*)&Cout[(size_t)r * NCOL + c] = o;
            }
        }
}

// =====================================================================
// split-bf16 3-pass GEMM.
// EP: 0 partial, 1 relu+bias, 3 +bias, 4 +bias+speaker,
//     5 dual-segment (by: 0 -> Ah/Al @ B[:, 0:200], 1 -> Ah2/Al2 @ B[:, 200:400])
// =====================================================================
__device__ __forceinline__ void load_stage(
    uint32_t sb, const __nv_bfloat16* __restrict__ Ah, const __nv_bfloat16* __restrict__ Al,
    int lda, const __nv_bfloat16* __restrict__ Bh, const __nv_bfloat16* __restrict__ Bl,
    int ldb, int row0, int M, int kb, int ke, int tid)
{
    for (int g = tid; g < 2816; g += 256) {
        const __nv_bfloat16* srow;
        uint32_t toff;
        int r, c;
        bool rv;
        if (g < 1024) {
            int t = g >> 9, idx = g & 511;
            r = idx >> 2; c = idx & 3;
            srow = (t ? Al : Ah);
            toff = t ? SA_L : SA_H;
            rv = (row0 + r) < M;
            if (rv) srow += (size_t)(row0 + r) * lda;
        } else {
            int gb = g - 1024;
            int t = gb >= 896;
            int idx = t ? gb - 896 : gb;
            r = idx >> 2; c = idx & 3;
            srow = (t ? Bl : Bh);
            toff = t ? SB_L : SB_H;
            rv = r < NCOL;
            if (rv) srow += (size_t)r * ldb;
        }
        int k0 = kb + c * 8;
        int sz = 0;
        const void* sp = srow;
        if (rv) {
            int kv = (ke - k0) * 2;
            sz = kv >= 16 ? 16 : (kv > 0 ? kv : 0);
            if (sz > 0) sp = srow + k0;
        }
        cp16(sb + toff + swz((uint32_t)(r * 64 + c * 16)), sp, sz);
    }
}

template <int EP>
__global__ __launch_bounds__(256)
void mma_gemm(const __nv_bfloat16* __restrict__ Ah, const __nv_bfloat16* __restrict__ Al, int lda,
              const __nv_bfloat16* __restrict__ Bh, const __nv_bfloat16* __restrict__ Bl, int ldb,
              int M, int Ktot, int ksize,
              float* __restrict__ Cbase,
              const float* __restrict__ bias,
              const float* __restrict__ aux0, const float* __restrict__ aux1,
              const __nv_bfloat16* __restrict__ Ah2, const __nv_bfloat16* __restrict__ Al2)
{
    extern __shared__ char dsm_raw[];
    const int tid  = threadIdx.x;
    const int wid  = tid >> 5;
    const int lane = tid & 31;
    const int wm   = wid >> 2;
    const int wn   = wid & 3;
    const int row0 = blockIdx.x * BMM;
    const int seg  = blockIdx.y;
    const int ks   = (EP == 5) ? 0 : seg * ksize;
    const int ke   = (EP == 5) ? Ktot : ((ks + ksize < Ktot) ? (ks + ksize) : Ktot);
    float* Cout = (EP == 0 || EP == 5) ? (Cbase + (size_t)seg * SFULL) : Cbase;

    const __nv_bfloat16* AhU = (EP == 5 && seg) ? Ah2 : Ah;
    const __nv_bfloat16* AlU = (EP == 5 && seg) ? Al2 : Al;
    const __nv_bfloat16* BhU = (EP == 5) ? (Bh + seg * NCOL) : Bh;
    const __nv_bfloat16* BlU = (EP == 5) ? (Bl + seg * NCOL) : Bl;

    const uint32_t base = (smem_u32(dsm_raw) + 1023u) & ~1023u;

    float acc[4][7][4];
#pragma unroll
    for (int mt = 0; mt < 4; mt++)
#pragma unroll
        for (int nt = 0; nt < 7; nt++)
#pragma unroll
            for (int q = 0; q < 4; q++) acc[mt][nt][q] = 0.0f;

    const int nck = (ke - ks + 31) >> 5;

    int issued = 0;
    for (; issued < nck && issued < NST - 1; issued++) {
        load_stage(base + issued * STAGE, AhU, AlU, lda, BhU, BlU, ldb,
                   row0, M, ks + issued * 32, ke, tid);
        cp_commit();
    }

    for (int i = 0; i < nck; i++) {
        if (nck - i >= 2) asm volatile("cp.async.wait_group 1;" ::: "memory");
        else              asm volatile("cp.async.wait_group 0;" ::: "memory");
        __syncthreads();
        if (issued < nck) {
            load_stage(base + (uint32_t)(issued % NST) * STAGE, AhU, AlU, lda, BhU, BlU, ldb,
                       row0, M, ks + issued * 32, ke, tid);
            cp_commit();
            issued++;
        }

        const uint32_t sb  = base + (uint32_t)(i % NST) * STAGE;
        const uint32_t aHu = sb + SA_H, aLu = sb + SA_L;
        const uint32_t bHu = sb + SB_H, bLu = sb + SB_L;

#pragma unroll
        for (int ksub = 0; ksub < 2; ksub++) {
            uint32_t ah[4][4], al[4][4];
#pragma unroll
            for (int mt = 0; mt < 4; mt++) {
                int r  = wm * 64 + mt * 16 + (lane & 15);
                int ch = 2 * ksub + (lane >> 4);
                uint32_t off = swz((uint32_t)(r * 64 + ch * 16));
                ldsm4(ah[mt], aHu + off);
                ldsm4(al[mt], aLu + off);
            }
#pragma unroll
            for (int nt = 0; nt < 7; nt++) {
                int rb = wn * 56 + nt * 8 + (lane & 7);
                int cb = 2 * ksub + ((lane >> 3) & 1);
                uint32_t off = swz((uint32_t)(rb * 64 + cb * 16));
                uint32_t bh[2], bl[2];
                ldsm2(bh, bHu + off);
                ldsm2(bl, bLu + off);
#pragma unroll
                for (int mt = 0; mt < 4; mt++) {
                    mma_bf(acc[mt][nt], ah[mt], bh);
                    mma_bf(acc[mt][nt], ah[mt], bl);
                    mma_bf(acc[mt][nt], al[mt], bh);
                }
            }
        }
    }

#pragma unroll
    for (int mt = 0; mt < 4; mt++) {
#pragma unroll
        for (int hf = 0; hf < 2; hf++) {
            const int r = row0 + wm * 64 + mt * 16 + (lane >> 2) + 8 * hf;
            if (r >= M) continue;
            int spk = 0;
            if (EP == 4) {
                int bI = r / 100, tI = r % 100;
                const float* q = aux0 + ((size_t)tI * 20 + bI) * 2;
                spk = (q[1] > q[0]) ? 1 : 0;
            }
#pragma unroll
            for (int nt = 0; nt < 7; nt++) {
                const int c = wn * 56 + nt * 8 + (lane & 3) * 2;
                if (c >= NCOL) continue;
                float vx = acc[mt][nt][2 * hf];
                float vy = acc[mt][nt][2 * hf + 1];
                if (EP == 1) {
                    vx = fmaxf(vx + bias[c], 0.0f);
                    vy = fmaxf(vy + bias[c + 1], 0.0f);
                } else if (EP == 3) {
                    vx += bias[c];
                    vy += bias[c + 1];
                } else if (EP == 4) {
                    vx += bias[c]     + aux1[spk * NCOL + c];
                    vy += bias[c + 1] + aux1[spk * NCOL + c + 1];
                }
                float2 o; o.x = vx; o.y = vy;
                *(float2*)&Cout[(size_t)r * NCOL + c] = o;
            }
        }
    }
}

// =====================================================================
// elementwise / conversion kernels (bandwidth-tuned)
// =====================================================================
// adj f32 -> fp16*2^14 : 32B in / 16B out per thread
__global__ void convert_adj(const float4* __restrict__ src, __half* __restrict__ dst) {
    int i = blockIdx.x * blockDim.x + threadIdx.x;          // over 36M/8
    if (i < NROW * NROW / 8) {
        float4 v0 = src[2 * i];
        float4 v1 = src[2 * i + 1];
        __half2 a = __floats2half2_rn(v0.x * ADJ_SCALE, v0.y * ADJ_SCALE);
        __half2 b = __floats2half2_rn(v0.z * ADJ_SCALE, v0.w * ADJ_SCALE);
        __half2 c = __floats2half2_rn(v1.x * ADJ_SCALE, v1.y * ADJ_SCALE);
        __half2 d = __floats2half2_rn(v1.z * ADJ_SCALE, v1.w * ADJ_SCALE);
        uint4 o;
        o.x = *(uint32_t*)&a; o.y = *(uint32_t*)&b;
        o.z = *(uint32_t*)&c; o.w = *(uint32_t*)&d;
        ((uint4*)dst)[i] = o;
    }
}

// f32 -> split bf16 (linear, vectorized)
__global__ void convert_split4(const float* __restrict__ src, int n4,
                               __nv_bfloat16* __restrict__ dh,
                               __nv_bfloat16* __restrict__ dl)
{
    int i = blockIdx.x * blockDim.x + threadIdx.x;
    if (i < n4) {
        float4 v = ((const float4*)src)[i];
        __nv_bfloat16 h0, l0, h1, l1, h2, l2, h3, l3;
        split_bf(v.x, h0, l0); split_bf(v.y, h1, l1);
        split_bf(v.z, h2, l2); split_bf(v.w, h3, l3);
        __nv_bfloat162* H = (__nv_bfloat162*)dh;
        __nv_bfloat162* L = (__nv_bfloat162*)dl;
        H[2 * i]     = __nv_bfloat162(h0, h1);
        H[2 * i + 1] = __nv_bfloat162(h2, h3);
        L[2 * i]     = __nv_bfloat162(l0, l1);
        L[2 * i + 1] = __nv_bfloat162(l2, l3);
    }
}

__global__ void padsplit(const float* __restrict__ src, int R, int C, int Cp,
                         __nv_bfloat16* __restrict__ dh, __nv_bfloat16* __restrict__ dl)
{
    int i = blockIdx.x * blockDim.x + threadIdx.x;
    if (i < R * Cp) {
        int r = i / Cp, c = i % Cp;
        float v = (c < C) ? src[(size_t)r * C + c] : 0.0f;
        __nv_bfloat16 h, l;
        split_bf(v, h, l);
        dh[i] = h; dl[i] = l;
    }
}

__global__ void tsplit(const float* __restrict__ src, int R, int C, int Rp,
                       __nv_bfloat16* __restrict__ dh, __nv_bfloat16* __restrict__ dl)
{
    __shared__ float t[32][33];
    int r = blockIdx.x * 32 + threadIdx.y;
    int c = blockIdx.y * 32 + threadIdx.x;
    if (r < R && c < C) t[threadIdx.y][threadIdx.x] = src[(size_t)r * C + c];
    __syncthreads();
    int rr = blockIdx.x * 32 + threadIdx.x;
    int cc = blockIdx.y * 32 + threadIdx.y;
    if (rr < Rp && cc < C) {
        float v = (rr < R) ? t[threadIdx.x][threadIdx.y] : 0.0f;
        __nv_bfloat16 h, l;
        split_bf(v, h, l);
        dh[(size_t)cc * Rp + rr] = h;
        dl[(size_t)cc * Rp + rr] = l;
    }
}

// batched W transposes: z=0 -> W0 [200,200], z=1..8 -> convW layer [400,200]
__global__ void tsplit_w(const float* __restrict__ W0, const float* __restrict__ convW) {
    __shared__ float t[32][33];
    int z = blockIdx.z;
    const float* src;
    __nv_bfloat16 *dh, *dl;
    int R;
    if (z == 0) { src = W0; dh = g_W0Th; dl = g_W0Tl; R = NCOL; }
    else {
        src = convW + (size_t)(z - 1) * 2 * NCOL * NCOL;
        dh = g_WTh8 + (size_t)(z - 1) * NCOL * 2 * NCOL;
        dl = g_WTl8 + (size_t)(z - 1) * NCOL * 2 * NCOL;
        R = 2 * NCOL;
    }
    int r = blockIdx.x * 32 + threadIdx.y;
    int c = blockIdx.y * 32 + threadIdx.x;
    if (r < R && c < NCOL) t[threadIdx.y][threadIdx.x] = src[(size_t)r * NCOL + c];
    __syncthreads();
    int rr = blockIdx.x * 32 + threadIdx.x;
    int cc = blockIdx.y * 32 + threadIdx.y;
    if (rr < R && cc < NCOL) {
        __nv_bfloat16 h, l;
        split_bf(t[threadIdx.x][threadIdx.y], h, l);
        dh[(size_t)cc * R + rr] = h;
        dl[(size_t)cc * R + rr] = l;
    }
}

// transpose h0 -> g_hT16 (once)
__global__ void t_f16(const float* __restrict__ src) {
    __shared__ float t[32][33];
    int r = blockIdx.x * 32 + threadIdx.y;
    int c = blockIdx.y * 32 + threadIdx.x;
    if (r < NROW && c < NCOL) t[threadIdx.y][threadIdx.x] = src[(size_t)r * NCOL + c];
    __syncthreads();
    int rr = blockIdx.x * 32 + threadIdx.x;
    int cc = blockIdx.y * 32 + threadIdx.y;
    if (rr < NROW && cc < NCOL)
        g_hT16[(size_t)cc * NROW + rr] = __float2half(t[threadIdx.x][threadIdx.y]);
}

// hi = (sum of 3 adj partials) * 2^-14 ; write f32 + linear bf16 split
__global__ void reduce_hi() {
    int i = blockIdx.x * blockDim.x + threadIdx.x;   // float4 over 300000
    if (i < SFULL / 4) {
        const float4* p = (const float4*)g_part;
        float4 a = p[i], b = p[i + SFULL / 4], c = p[i + SFULL / 2];
        float4 s;
        s.x = (a.x + b.x + c.x) * ADJ_ISCALE;
        s.y = (a.y + b.y + c.y) * ADJ_ISCALE;
        s.z = (a.z + b.z + c.z) * ADJ_ISCALE;
        s.w = (a.w + b.w + c.w) * ADJ_ISCALE;
        ((float4*)g_hi)[i] = s;
        __nv_bfloat16 h0, l0, h1, l1, h2, l2, h3, l3;
        split_bf(s.x, h0, l0); split_bf(s.y, h1, l1);
        split_bf(s.z, h2, l2); split_bf(s.w, h3, l3);
        __nv_bfloat162 H0(h0, h1), H1(h2, h3), L0(l0, l1), L1(l2, l3);
        uint2 oh, ol;
        oh.x = *(uint32_t*)&H0; oh.y = *(uint32_t*)&H1;
        ol.x = *(uint32_t*)&L0; ol.y = *(uint32_t*)&L1;
        ((uint2*)g_hih)[i] = oh;
        ((uint2*)g_hil)[i] = ol;
    }
}

// combine 2 S@W partials + GCNII + relu -> g_h ; also write h^T fp16
__global__ void reduce_gcnii(float theta) {
    __shared__ float t[32][33];
    const int r0 = blockIdx.x * 32;
    const int c0 = blockIdx.y * 32;
#pragma unroll
    for (int q = 0; q < 4; q++) {
        int r = r0 + threadIdx.y * 4 + q;
        int c = c0 + threadIdx.x;
        float val = 0.0f;
        if (r < NROW && c < NCOL) {
            int i = r * NCOL + c;
            float sw = g_part[i] + g_part[i + SFULL];
            float rr = 0.9f * g_hi[i] + 0.1f * g_h0[i];
            val = fmaxf(theta * sw + (1.0f - theta) * rr, 0.0f);
            g_h[i] = val;
        }
        t[threadIdx.y * 4 + q][threadIdx.x] = val;
    }
    __syncthreads();
#pragma unroll
    for (int q = 0; q < 4; q++) {
        int rr2 = r0 + threadIdx.x;
        int cc  = c0 + threadIdx.y * 4 + q;
        if (rr2 < NROW && cc < NCOL)
            g_hT16[(size_t)cc * NROW + rr2] = __float2half(t[threadIdx.x][threadIdx.y * 4 + q]);
    }
}

// out[i, m*400+j] gather, float4
__global__ void assemble_kernel(float4* __restrict__ out) {
    int i4 = blockIdx.x * blockDim.x + threadIdx.x;   // over 600000
    if (i4 < NUTT * 300) {
        int row = i4 / 300;
        int c4  = i4 % 300;
        int m   = c4 / 100;
        int j   = c4 % 100;
        const float4* src = (j < 50) ? (const float4*)g_x : (const float4*)g_h;
        out[i4] = src[(size_t)(m * NUTT + row) * 50 + (j % 50)];
    }
}

// =====================================================================
extern "C" void kernel_launch(void* const* d_in, const int* in_sizes, int n_in,
                              void* d_out, int out_size)
{
    const float* a     = (const float*)d_in[0];
    const float* v     = (const float*)d_in[1];
    const float* l     = (const float*)d_in[2];
    const float* qmask = (const float*)d_in[3];
    const float* adj   = (const float*)d_in[4];
    const float* Wa    = (const float*)d_in[5];
    const float* ba    = (const float*)d_in[6];
    const float* Wv    = (const float*)d_in[7];
    const float* bv    = (const float*)d_in[8];
    const float* Wl    = (const float*)d_in[9];
    const float* bl    = (const float*)d_in[10];
    const float* spk   = (const float*)d_in[11];
    const float* W0    = (const float*)d_in[12];
    const float* b0    = (const float*)d_in[13];
    const float* convW = (const float*)d_in[14];
    float* out = (float*)d_out;

    float *gx, *gh0, *gpart;
    __half *adj16, *hT16;
    __nv_bfloat16 *hih, *hil, *h0h, *h0l, *WTh8, *WTl8, *W0Th, *W0Tl, *xh, *xl;
    __nv_bfloat16 *ah_, *al_, *vh_, *vl_, *lh_, *ll_;
    __nv_bfloat16 *WaTh, *WaTl, *WvTh, *WvTl, *WlTh, *WlTl;
    cudaGetSymbolAddress((void**)&gx,    g_x);
    cudaGetSymbolAddress((void**)&gh0,   g_h0);
    cudaGetSymbolAddress((void**)&gpart, g_part);
    cudaGetSymbolAddress((void**)&adj16, g_adj16);
    cudaGetSymbolAddress((void**)&hT16,  g_hT16);
    cudaGetSymbolAddress((void**)&hih,   g_hih);
    cudaGetSymbolAddress((void**)&hil,   g_hil);
    cudaGetSymbolAddress((void**)&h0h,   g_h0h);
    cudaGetSymbolAddress((void**)&h0l,   g_h0l);
    cudaGetSymbolAddress((void**)&WTh8,  g_WTh8);
    cudaGetSymbolAddress((void**)&WTl8,  g_WTl8);
    cudaGetSymbolAddress((void**)&W0Th,  g_W0Th);
    cudaGetSymbolAddress((void**)&W0Tl,  g_W0Tl);
    cudaGetSymbolAddress((void**)&xh,    g_xh);
    cudaGetSymbolAddress((void**)&xl,    g_xl);
    cudaGetSymbolAddress((void**)&ah_,   g_ah_);
    cudaGetSymbolAddress((void**)&al_,   g_al_);
    cudaGetSymbolAddress((void**)&vh_,   g_vh_);
    cudaGetSymbolAddress((void**)&vl_,   g_vl_);
    cudaGetSymbolAddress((void**)&lh_,   g_lh_);
    cudaGetSymbolAddress((void**)&ll_,   g_ll_);
    cudaGetSymbolAddress((void**)&WaTh,  g_WaTh);
    cudaGetSymbolAddress((void**)&WaTl,  g_WaTl);
    cudaGetSymbolAddress((void**)&WvTh,  g_WvTh);
    cudaGetSymbolAddress((void**)&WvTl,  g_WvTl);
    cudaGetSymbolAddress((void**)&WlTh,  g_WlTh);
    cudaGetSymbolAddress((void**)&WlTl,  g_WlTl);

    cudaFuncSetAttribute(mma_f16,     cudaFuncAttributeMaxDynamicSharedMemorySize, F_DSMEM);
    cudaFuncSetAttribute(mma_gemm<1>, cudaFuncAttributeMaxDynamicSharedMemorySize, DSMEM);
    cudaFuncSetAttribute(mma_gemm<3>, cudaFuncAttributeMaxDynamicSharedMemorySize, DSMEM);
    cudaFuncSetAttribute(mma_gemm<4>, cudaFuncAttributeMaxDynamicSharedMemorySize, DSMEM);
    cudaFuncSetAttribute(mma_gemm<5>, cudaFuncAttributeMaxDynamicSharedMemorySize, DSMEM);

    // ---- one-time conversions ----
    convert_adj<<<(NROW * NROW / 8 + 255) / 256, 256>>>((const float4*)adj, adj16);
    padsplit<<<(2000 * 304 + 255) / 256, 256>>>(a, 2000, 300,  304,  ah_, al_);
    padsplit<<<(2000 * 352 + 255) / 256, 256>>>(v, 2000, 342,  352,  vh_, vl_);
    padsplit<<<(2000 * 1024 + 255) / 256, 256>>>(l, 2000, 1024, 1024, lh_, ll_);
    tsplit<<<dim3(10, 7), dim3(32, 32)>>>(Wa, 300,  NCOL, 304,  WaTh, WaTl);
    tsplit<<<dim3(11, 7), dim3(32, 32)>>>(Wv, 342,  NCOL, 352,  WvTh, WvTl);
    tsplit<<<dim3(32, 7), dim3(32, 32)>>>(Wl, 1024, NCOL, 1024, WlTh, WlTl);
    tsplit_w<<<dim3(13, 7, 9), dim3(32, 32)>>>(W0, convW);

    // ---- modality projections -> g_x ----
    const int gProj = (NUTT + BMM - 1) / BMM;    // 16
    const int gFull = (NROW + BMM - 1) / BMM;    // 47
    mma_gemm<3><<<dim3(gProj, 1), 256, DSMEM>>>(ah_, al_, 304, WaTh, WaTl, 304,
        NUTT, 304, 304, gx, ba, nullptr, nullptr, nullptr, nullptr);
    mma_gemm<3><<<dim3(gProj, 1), 256, DSMEM>>>(vh_, vl_, 352, WvTh, WvTl, 352,
        NUTT, 352, 352, gx + (size_t)NUTT * NCOL, bv, nullptr, nullptr, nullptr, nullptr);
    mma_gemm<4><<<dim3(gProj, 1), 256, DSMEM>>>(lh_, ll_, 1024, WlTh, WlTl, 1024,
        NUTT, 1024, 1024, gx + (size_t)2 * NUTT * NCOL, bl, qmask, spk, nullptr, nullptr);

    // ---- h0 = relu(x @ W0 + b0) ----
    convert_split4<<<(SFULL / 4 + 255) / 256, 256>>>(gx, SFULL / 4, xh, xl);
    mma_gemm<1><<<dim3(gFull, 1), 256, DSMEM>>>(xh, xl, NCOL, W0Th, W0Tl, NCOL,
        NROW, NCOL, NCOL, gh0, b0, nullptr, nullptr, nullptr, nullptr);
    convert_split4<<<(SFULL / 4 + 255) / 256, 256>>>(gh0, SFULL / 4, h0h, h0l);
    t_f16<<<dim3(188, 7), dim3(32, 32)>>>(gh0);

    // ---- GCNII layers ----
    for (int lay = 0; lay < NLAY; lay++) {
        float theta = logf(0.5f / (float)(lay + 1) + 1.0f);

        // hi partials = (adj*2^14) @ h   (fp16, K split 3)
        mma_f16<<<dim3(gFull, 3), 256, F_DSMEM>>>(adj16, NROW, hT16, NROW,
            NROW, NROW, 2000, gpart);
        reduce_hi<<<(SFULL / 4 + 255) / 256, 256>>>();

        // S@W = hi @ W[:200] + h0 @ W[200:]  (dual-segment, 2 partials)
        const __nv_bfloat16* Wh = WTh8 + (size_t)lay * NCOL * 2 * NCOL;
        const __nv_bfloat16* Wl2 = WTl8 + (size_t)lay * NCOL * 2 * NCOL;
        mma_gemm<5><<<dim3(gFull, 2), 256, DSMEM>>>(hih, hil, NCOL, Wh, Wl2, 2 * NCOL,
            NROW, NCOL, NCOL, gpart, nullptr, nullptr, nullptr, h0h, h0l);

        // combine + relu -> g_h ; write h^T fp16 for next layer
        reduce_gcnii<<<dim3(188, 7), dim3(32, 8)>>>(theta);
    }

    assemble_kernel<<<(NUTT * 300 + 255) / 256, 256>>>((float4*)out);
}